// round 1
// baseline (speedup 1.0000x reference)
#include <cuda_runtime.h>
#include <cuda_bf16.h>
#include <math.h>

// ---------------- problem constants ----------------
#define NH    768            // H
#define HEADS 8
#define HO    6144           // HEADS*H
#define TSTEP 3
#define BB    128            // molecules
#define NATOM 48
#define NPG   49             // nodes per graph
#define EPG   144            // edges per graph
#define NN    6272           // B*NPG nodes
#define EE    18432          // B*EPG edges
#define H3    2304           // 3*H

// ---------------- device scratch (no allocation allowed) ----------------
__device__ float g_h   [(size_t)NN * NH];    // current node features
__device__ float g_fs  [(size_t)NN * HO];    // feat_src  [N, heads*H]
__device__ float g_fd  [(size_t)NN * HO];    // feat_dst  [N, heads*H]
__device__ float g_logit[(size_t)EE * HEADS];
__device__ float g_amean[(size_t)EE];
__device__ float g_mol [(size_t)BB * NH];
__device__ float g_gi  [(size_t)BB * H3];
__device__ float g_gh  [(size_t)BB * H3];

// ---------------- init: copy inputs into device state ----------------
__global__ void init_k(const float* __restrict__ h_nodes, const float* __restrict__ mol)
{
    long i = (long)blockIdx.x * 256 + threadIdx.x;
    const long tot = (long)NN * NH;
    if (i < tot) g_h[i] = h_nodes[i];
    else if (i < tot + (long)BB * NH) g_mol[i - tot] = mol[i - tot];
}

// ---------------- fp32 tiled GEMM: C[sel] = g_h @ W + bias ----------------
// M=6272, K=768, N=6144; BM=BN=128, BK=16; 256 threads; 8x8 per thread
__global__ __launch_bounds__(256, 2) void gemm_fsfd(
    const float* __restrict__ W, const float* __restrict__ bias, int sel)
{
    __shared__ float As[16][128];
    __shared__ float Bs[16][128];
    float* C = sel ? g_fd : g_fs;
    const float* A = g_h;

    const int bm = blockIdx.y * 128;
    const int bn = blockIdx.x * 128;
    const int tid = threadIdx.x;
    const int ty = tid >> 4, tx = tid & 15;

    float acc[8][8];
    #pragma unroll
    for (int i = 0; i < 8; i++)
        #pragma unroll
        for (int j = 0; j < 8; j++) acc[i][j] = 0.f;

    for (int k0 = 0; k0 < NH; k0 += 16) {
        // A tile: 128 rows x 16 cols (512 float4, 2 per thread), store transposed
        #pragma unroll
        for (int l = 0; l < 2; l++) {
            int f  = tid * 2 + l;
            int r  = f >> 2;
            int cv = (f & 3) << 2;
            float4 v = *(const float4*)&A[(size_t)(bm + r) * NH + k0 + cv];
            As[cv + 0][r] = v.x; As[cv + 1][r] = v.y;
            As[cv + 2][r] = v.z; As[cv + 3][r] = v.w;
        }
        // B tile: 16 rows x 128 cols (512 float4, 2 per thread)
        #pragma unroll
        for (int l = 0; l < 2; l++) {
            int f  = tid * 2 + l;
            int r  = f >> 5;
            int cv = (f & 31) << 2;
            *(float4*)&Bs[r][cv] = *(const float4*)&W[(size_t)(k0 + r) * HO + bn + cv];
        }
        __syncthreads();
        #pragma unroll
        for (int k = 0; k < 16; k++) {
            float a[8], b[8];
            *(float4*)&a[0] = *(float4*)&As[k][ty * 8];
            *(float4*)&a[4] = *(float4*)&As[k][ty * 8 + 4];
            *(float4*)&b[0] = *(float4*)&Bs[k][tx * 8];
            *(float4*)&b[4] = *(float4*)&Bs[k][tx * 8 + 4];
            #pragma unroll
            for (int i = 0; i < 8; i++)
                #pragma unroll
                for (int j = 0; j < 8; j++)
                    acc[i][j] = fmaf(a[i], b[j], acc[i][j]);
        }
        __syncthreads();
    }

    #pragma unroll
    for (int i = 0; i < 8; i++) {
        size_t row = (size_t)(bm + ty * 8 + i) * HO;
        #pragma unroll
        for (int j = 0; j < 8; j += 4) {
            int col = bn + tx * 8 + j;
            float4 v;
            v.x = acc[i][j + 0] + bias[col + 0];
            v.y = acc[i][j + 1] + bias[col + 1];
            v.z = acc[i][j + 2] + bias[col + 2];
            v.w = acc[i][j + 3] + bias[col + 3];
            *(float4*)&C[row + col] = v;
        }
    }
}

// ---------------- edge logits: per (edge, head) warp ----------------
__global__ void edge_logits_k(const int* __restrict__ src, const int* __restrict__ dst,
                              const float* __restrict__ attn_a /* offset by t */)
{
    const int e = blockIdx.x;
    const int w = threadIdx.x >> 5, lane = threadIdx.x & 31;
    const int s = src[e], d = dst[e];
    const float* fsr = &g_fs[(size_t)s * HO + w * NH];
    const float* fdr = &g_fd[(size_t)d * HO + w * NH];
    const float* aa  = &attn_a[w * NH];
    float acc = 0.f;
    for (int i = lane; i < NH; i += 32) {
        float v = fsr[i] + fdr[i];
        v = v > 0.f ? v : 0.2f * v;        // leaky_relu(0.2)
        acc = fmaf(v, aa[i], acc);
    }
    #pragma unroll
    for (int o = 16; o > 0; o >>= 1) acc += __shfl_xor_sync(0xFFFFFFFFu, acc, o);
    if (lane == 0) g_logit[(size_t)e * HEADS + w] = acc;
}

// ---------------- per-node softmax + aggregation (no atomics) ----------------
// Every edge's dst lives in its own graph's contiguous [g*EPG, (g+1)*EPG) range.
__global__ __launch_bounds__(256) void node_aggregate_k(
    const int* __restrict__ src, const int* __restrict__ dst)
{
    const int n = blockIdx.x;
    const int tid = threadIdx.x;
    __shared__ int   cnt;
    __shared__ int   eidx[EPG];
    __shared__ int   esrc[EPG];
    __shared__ float w[EPG];
    __shared__ float am[EPG];
    __shared__ float red[256];

    const int g = n / NPG;
    if (tid == 0) cnt = 0;
    __syncthreads();
    if (tid < EPG) {
        int e = g * EPG + tid;
        if (dst[e] == n) {
            int p = atomicAdd(&cnt, 1);   // smem atomic only, tiny
            eidx[p] = e;
            esrc[p] = src[e];
        }
    }
    __syncthreads();
    const int deg = cnt;

    float h0 = 0.f, h1 = 0.f, h2 = 0.f;   // d = tid, tid+256, tid+512

    if (deg > 0) {
        for (int hh = 0; hh < HEADS; hh++) {
            // max over incoming logits
            float lm = -1e30f;
            for (int i = tid; i < deg; i += 256)
                lm = fmaxf(lm, g_logit[(size_t)eidx[i] * HEADS + hh]);
            red[tid] = lm; __syncthreads();
            for (int s2 = 128; s2 > 0; s2 >>= 1) {
                if (tid < s2) red[tid] = fmaxf(red[tid], red[tid + s2]);
                __syncthreads();
            }
            float m = red[0]; __syncthreads();
            // exp + sum
            float ls = 0.f;
            for (int i = tid; i < deg; i += 256) {
                float ex = expf(g_logit[(size_t)eidx[i] * HEADS + hh] - m);
                w[i] = ex; ls += ex;
            }
            red[tid] = ls; __syncthreads();
            for (int s2 = 128; s2 > 0; s2 >>= 1) {
                if (tid < s2) red[tid] += red[tid + s2];
                __syncthreads();
            }
            float inv = 1.f / red[0]; __syncthreads();
            for (int i = tid; i < deg; i += 256) {
                float wi = w[i] * inv;
                w[i] = wi;
                float prev = (hh == 0) ? 0.f : am[i];
                am[i] = prev + wi * 0.125f;     // mean over heads
            }
            __syncthreads();
            // feature accumulation: rst[n,h,:] = sum_e w_e * fs[src_e,h,:]
            const int bh = hh * NH;
            for (int e = 0; e < deg; e++) {
                float we = w[e];
                const float* fr = &g_fs[(size_t)esrc[e] * HO + bh];
                h0 = fmaf(we, fr[tid      ], h0);
                h1 = fmaf(we, fr[tid + 256], h1);
                h2 = fmaf(we, fr[tid + 512], h2);
            }
            __syncthreads();   // protect w[] before next head
        }
    }
    // mean over heads
    g_h[(size_t)n * NH + tid      ] = h0 * 0.125f;
    g_h[(size_t)n * NH + tid + 256] = h1 * 0.125f;
    g_h[(size_t)n * NH + tid + 512] = h2 * 0.125f;
    for (int i = tid; i < deg; i += 256) g_amean[eidx[i]] = am[i];
}

// ---------------- attention gather to output ----------------
__global__ void attn_gather_k(const int* __restrict__ eids, float* __restrict__ out, int t)
{
    int i = blockIdx.x * 256 + threadIdx.x;
    if (i < BB * NATOM)
        out[(size_t)BB * NH + (size_t)t * BB * NATOM + i] = g_amean[eids[i]];
}

// ---------------- GRU gemms: warp per (b, j) output ----------------
__global__ void gru_gemm_k(const float* __restrict__ W_ih, const float* __restrict__ W_hh,
                           const float* __restrict__ b_ih, const float* __restrict__ b_hh,
                           const int* __restrict__ vnid)
{
    const int p = blockIdx.x * 8 + (threadIdx.x >> 5);
    const int lane = threadIdx.x & 31;
    const int b = p / H3, j = p % H3;
    const float* x  = &g_h[(size_t)vnid[b] * NH];
    const float* hp = &g_mol[(size_t)b * NH];
    const float* wi = &W_ih[(size_t)j * NH];
    const float* wh = &W_hh[(size_t)j * NH];
    float ai = 0.f, ah = 0.f;
    for (int k = lane; k < NH; k += 32) {
        ai = fmaf(x[k],  wi[k], ai);
        ah = fmaf(hp[k], wh[k], ah);
    }
    #pragma unroll
    for (int o = 16; o > 0; o >>= 1) {
        ai += __shfl_xor_sync(0xFFFFFFFFu, ai, o);
        ah += __shfl_xor_sync(0xFFFFFFFFu, ah, o);
    }
    if (lane == 0) {
        g_gi[(size_t)b * H3 + j] = ai + b_ih[j];
        g_gh[(size_t)b * H3 + j] = ah + b_hh[j];
    }
}

// ---------------- GRU combine + relu ----------------
__global__ void gru_combine_k(float* __restrict__ out_mol, int write_out)
{
    int i = blockIdx.x * 256 + threadIdx.x;   // < B*H
    int b = i / NH, k = i % NH;
    size_t base = (size_t)b * H3;
    float ir = g_gi[base + k], iz = g_gi[base + NH + k], in_ = g_gi[base + 2 * NH + k];
    float hr = g_gh[base + k], hz = g_gh[base + NH + k], hn  = g_gh[base + 2 * NH + k];
    float r  = 1.f / (1.f + expf(-(ir + hr)));
    float z  = 1.f / (1.f + expf(-(iz + hz)));
    float nn = tanhf(in_ + r * hn);
    float hprev = g_mol[i];
    float hnew  = (1.f - z) * nn + z * hprev;
    hnew = fmaxf(hnew, 0.f);                  // relu in reference
    g_mol[i] = hnew;
    if (write_out) out_mol[i] = hnew;
}

// ---------------- launch ----------------
extern "C" void kernel_launch(void* const* d_in, const int* in_sizes, int n_in,
                              void* d_out, int out_size)
{
    const float* h_nodes  = (const float*)d_in[0];
    const float* mol_feat = (const float*)d_in[1];
    const float* W_src    = (const float*)d_in[2];
    const float* b_src    = (const float*)d_in[3];
    const float* W_dst    = (const float*)d_in[4];
    const float* b_dst    = (const float*)d_in[5];
    const float* attn_a   = (const float*)d_in[6];
    const float* W_ih     = (const float*)d_in[7];
    const float* W_hh     = (const float*)d_in[8];
    const float* b_ih     = (const float*)d_in[9];
    const float* b_hh     = (const float*)d_in[10];
    const int*   src      = (const int*)d_in[11];
    const int*   dst      = (const int*)d_in[12];
    const int*   vnid     = (const int*)d_in[13];
    const int*   eids     = (const int*)d_in[14];
    float* out = (float*)d_out;

    {
        long tot = (long)NN * NH + (long)BB * NH;
        init_k<<<(int)((tot + 255) / 256), 256>>>(h_nodes, mol_feat);
    }

    for (int t = 0; t < TSTEP; t++) {
        dim3 gg(HO / 128, NN / 128);   // (48, 49)
        gemm_fsfd<<<gg, 256>>>(W_src + (size_t)t * NH * HO, b_src + (size_t)t * HO, 0);
        gemm_fsfd<<<gg, 256>>>(W_dst + (size_t)t * NH * HO, b_dst + (size_t)t * HO, 1);
        edge_logits_k<<<EE, 256>>>(src, dst, attn_a + (size_t)t * HEADS * NH);
        node_aggregate_k<<<NN, 256>>>(src, dst);
        attn_gather_k<<<(BB * NATOM + 255) / 256, 256>>>(eids, out, t);
        gru_gemm_k<<<BB * H3 / 8, 256>>>(W_ih + (size_t)t * H3 * NH,
                                         W_hh + (size_t)t * H3 * NH,
                                         b_ih + (size_t)t * H3,
                                         b_hh + (size_t)t * H3, vnid);
        gru_combine_k<<<BB * NH / 256, 256>>>(out, t == TSTEP - 1);
    }
}

// round 3
// speedup vs baseline: 1.8297x; 1.8297x over previous
#include <cuda_runtime.h>
#include <cuda_bf16.h>
#include <math.h>
#include <stdint.h>

// ---------------- problem constants ----------------
#define NH    768            // H
#define HEADS 8
#define HO    6144           // HEADS*H
#define TSTEP 3
#define BB    128            // molecules
#define NATOM 48
#define NPG   49             // nodes per graph
#define EPG   144            // edges per graph
#define NN    6272           // B*NPG nodes
#define EE    18432          // B*EPG edges
#define H3    2304           // 3*H

// ---------------- device scratch (no allocation allowed) ----------------
__device__ float g_h   [(size_t)NN * NH];    // current node features (fp32)
__device__ float g_fs  [(size_t)NN * HO];    // feat_src  [N, heads*H]
__device__ float g_fd  [(size_t)NN * HO];    // feat_dst  [N, heads*H]
__device__ float g_logit[(size_t)EE * HEADS];
__device__ float g_amean[(size_t)EE];
__device__ float g_mol [(size_t)BB * NH];
__device__ float g_gi  [(size_t)BB * H3];
__device__ float g_gh  [(size_t)BB * H3];

// bf16 split operands for tensor-core GEMM
__device__ __nv_bfloat16 g_Ahi[(size_t)NN * NH];
__device__ __nv_bfloat16 g_Alo[(size_t)NN * NH];
// 6 weight matrices (t*2 + sel), transposed to [N=6144, K=768]
__device__ __nv_bfloat16 g_Bhi[(size_t)6 * HO * NH];
__device__ __nv_bfloat16 g_Blo[(size_t)6 * HO * NH];

// ---------------- init: copy inputs into device state ----------------
__global__ void init_k(const float* __restrict__ h_nodes, const float* __restrict__ mol)
{
    long i = (long)blockIdx.x * 256 + threadIdx.x;
    const long tot = (long)NN * NH;
    if (i < tot) g_h[i] = h_nodes[i];
    else if (i < tot + (long)BB * NH) g_mol[i - tot] = mol[i - tot];
}

// ---------------- transpose + bf16-split all 6 weight matrices ----------------
// W: [768, 6144] row-major -> g_B{hi,lo}[mat][n][k]  ([6144, 768])
__global__ void transpose_conv_k(const float* __restrict__ Wsrc, const float* __restrict__ Wdst)
{
    const int mat = blockIdx.z;                    // t*2 + sel
    const float* W = ((mat & 1) ? Wdst : Wsrc) + (size_t)(mat >> 1) * NH * HO;
    __shared__ float tile[32][33];
    const int n0 = blockIdx.x * 32, k0 = blockIdx.y * 32;
    const int tx = threadIdx.x, ty = threadIdx.y;  // 32 x 8
    #pragma unroll
    for (int i = ty; i < 32; i += 8)
        tile[i][tx] = W[(size_t)(k0 + i) * HO + n0 + tx];
    __syncthreads();
    const size_t base = (size_t)mat * HO * NH;
    #pragma unroll
    for (int i = ty; i < 32; i += 8) {
        float v = tile[tx][i];                      // = W[k0+tx][n0+i]
        __nv_bfloat16 hi = __float2bfloat16(v);
        __nv_bfloat16 lo = __float2bfloat16(v - __bfloat162float(hi));
        size_t o = base + (size_t)(n0 + i) * NH + k0 + tx;
        g_Bhi[o] = hi;
        g_Blo[o] = lo;
    }
}

// ---------------- split g_h into bf16 hi/lo ----------------
__global__ void convert_A_k()
{
    long i = (long)blockIdx.x * 256 + threadIdx.x;
    if (i < (long)NN * NH) {
        float v = g_h[i];
        __nv_bfloat16 hi = __float2bfloat16(v);
        g_Ahi[i] = hi;
        g_Alo[i] = __float2bfloat16(v - __bfloat162float(hi));
    }
}

// ================= mma.sync bf16 GEMM (base sm_103 PTX features only) ==========
// C[6272,6144] = A[6272,768] * B^T  (B stored [6144,768], K-contiguous)
// 3-term split precision: Ahi*Bhi + Alo*Bhi + Ahi*Blo, fp32 accum.
// Block tile 128x128, K-chunk 32, cp.async double buffer, 8 warps (4m x 2n),
// warp tile 32m x 64n -> 2 mfrag x 8 nfrag of m16n8k16.

#define KC      32
#define TILE_B  8192                       // one 128x32 bf16 tile
#define ST_AHI  0
#define ST_ALO  8192
#define ST_BHI  16384
#define ST_BLO  24576
#define ST_SZ   32768                      // per stage
#define GEMM_SMEM (2 * ST_SZ)              // 64 KB

__device__ __forceinline__ void cp16(uint32_t saddr, const void* gaddr) {
    asm volatile("cp.async.cg.shared.global [%0], [%1], 16;" :: "r"(saddr), "l"(gaddr) : "memory");
}
__device__ __forceinline__ void cp_commit() { asm volatile("cp.async.commit_group;" ::: "memory"); }
template <int N> __device__ __forceinline__ void cp_wait() {
    asm volatile("cp.async.wait_group %0;" :: "n"(N) : "memory");
}
__device__ __forceinline__ void ldsm4(uint32_t r[4], uint32_t addr) {
    asm volatile("ldmatrix.sync.aligned.m8n8.x4.shared.b16 {%0,%1,%2,%3}, [%4];"
        : "=r"(r[0]), "=r"(r[1]), "=r"(r[2]), "=r"(r[3]) : "r"(addr));
}
__device__ __forceinline__ void mma_bf16(float c[4], const uint32_t a[4], const uint32_t b[2]) {
    asm volatile("mma.sync.aligned.m16n8k16.row.col.f32.bf16.bf16.f32 "
        "{%0,%1,%2,%3}, {%4,%5,%6,%7}, {%8,%9}, {%0,%1,%2,%3};"
        : "+f"(c[0]), "+f"(c[1]), "+f"(c[2]), "+f"(c[3])
        : "r"(a[0]), "r"(a[1]), "r"(a[2]), "r"(a[3]), "r"(b[0]), "r"(b[1]));
}
__device__ __forceinline__ uint32_t smem_u32(const void* p) {
    uint32_t a;
    asm("{ .reg .u64 t; cvta.to.shared.u64 t, %1; cvt.u32.u64 %0, t; }" : "=r"(a) : "l"(p));
    return a;
}

__global__ void gemm_mma(const __nv_bfloat16* __restrict__ Bhi,
                         const __nv_bfloat16* __restrict__ Blo,
                         const float* __restrict__ bias, float* __restrict__ C)
{
    extern __shared__ char sm[];
    const uint32_t sb = smem_u32(sm);
    const int tid  = threadIdx.x;
    const int wid  = tid >> 5, lane = tid & 31;
    const int m0   = blockIdx.y * 128, n0 = blockIdx.x * 128;
    const int wm   = wid & 3;           // 0..3 -> 32-row slice
    const int wn   = wid >> 2;          // 0..1 -> 64-col slice

    // ---- cp.async tile loader: thread -> 2 (row,seg) pairs, 4 tiles each ----
    // seg = 8 bf16 = 16B; row stride in smem = 64B; swizzle seg ^= (row & 3)
    const int seg0 = tid * 2;
    const int r0l  = seg0 >> 2,  c0l = seg0 & 3;
    const int r1l  = (seg0 + 1) >> 2, c1l = (seg0 + 1) & 3;
    const uint32_t so0 = r0l * 64 + ((c0l ^ (r0l & 3)) << 4);
    const uint32_t so1 = r1l * 64 + ((c1l ^ (r1l & 3)) << 4);

    #define LOAD_STAGE(stg, k0) do {                                              \
        uint32_t _b = sb + (stg) * ST_SZ;                                         \
        size_t ga0 = (size_t)(m0 + r0l) * NH + (k0) + c0l * 8;                    \
        size_t ga1 = (size_t)(m0 + r1l) * NH + (k0) + c1l * 8;                    \
        size_t gb0 = (size_t)(n0 + r0l) * NH + (k0) + c0l * 8;                    \
        size_t gb1 = (size_t)(n0 + r1l) * NH + (k0) + c1l * 8;                    \
        cp16(_b + ST_AHI + so0, g_Ahi + ga0);                                     \
        cp16(_b + ST_AHI + so1, g_Ahi + ga1);                                     \
        cp16(_b + ST_ALO + so0, g_Alo + ga0);                                     \
        cp16(_b + ST_ALO + so1, g_Alo + ga1);                                     \
        cp16(_b + ST_BHI + so0, Bhi + gb0);                                       \
        cp16(_b + ST_BHI + so1, Bhi + gb1);                                       \
        cp16(_b + ST_BLO + so0, Blo + gb0);                                       \
        cp16(_b + ST_BLO + so1, Blo + gb1);                                       \
    } while (0)

    // ---- per-lane ldmatrix addressing ----
    const int sub = lane >> 3, rin = lane & 7;
    const int aRow0 = wm * 32 + (sub & 1) * 8 + rin;   // + mf*16
    const int aSegB = sub >> 1;                        // + k16/8
    const int bRow0 = wn * 64 + (sub >> 1) * 8 + rin;  // + p*16
    const int bSegB = sub & 1;                         // + k16/8

    float acc[16][4];
    #pragma unroll
    for (int i = 0; i < 16; i++)
        #pragma unroll
        for (int j = 0; j < 4; j++) acc[i][j] = 0.f;

    LOAD_STAGE(0, 0);
    cp_commit();

    const int NCH = NH / KC;   // 24
    for (int kc = 0; kc < NCH; kc++) {
        const int stg = kc & 1;
        if (kc + 1 < NCH) {
            LOAD_STAGE((kc + 1) & 1, (kc + 1) * KC);
            cp_commit();
            cp_wait<1>();
        } else {
            cp_wait<0>();
        }
        __syncthreads();

        const uint32_t stb = sb + stg * ST_SZ;
        #pragma unroll
        for (int k16 = 0; k16 < 2; k16++) {
            const int ks = k16 * 2;   // k-seg base (0 or 2)
            uint32_t aH[2][4], aL[2][4], bb[8][2];
            #pragma unroll
            for (int mf = 0; mf < 2; mf++) {
                int row = aRow0 + mf * 16;
                uint32_t off = row * 64 + (((ks + aSegB) ^ (row & 3)) << 4);
                ldsm4(aH[mf], stb + ST_AHI + off);
                ldsm4(aL[mf], stb + ST_ALO + off);
            }
            #pragma unroll
            for (int pp = 0; pp < 4; pp++) {
                int row = bRow0 + pp * 16;
                uint32_t off = row * 64 + (((ks + bSegB) ^ (row & 3)) << 4);
                uint32_t t[4];
                ldsm4(t, stb + ST_BHI + off);
                bb[pp * 2][0] = t[0]; bb[pp * 2][1] = t[1];
                bb[pp * 2 + 1][0] = t[2]; bb[pp * 2 + 1][1] = t[3];
            }
            #pragma unroll
            for (int mf = 0; mf < 2; mf++)
                #pragma unroll
                for (int p = 0; p < 8; p++) mma_bf16(acc[mf * 8 + p], aH[mf], bb[p]);
            #pragma unroll
            for (int mf = 0; mf < 2; mf++)
                #pragma unroll
                for (int p = 0; p < 8; p++) mma_bf16(acc[mf * 8 + p], aL[mf], bb[p]);
            #pragma unroll
            for (int pp = 0; pp < 4; pp++) {
                int row = bRow0 + pp * 16;
                uint32_t off = row * 64 + (((ks + bSegB) ^ (row & 3)) << 4);
                uint32_t t[4];
                ldsm4(t, stb + ST_BLO + off);
                bb[pp * 2][0] = t[0]; bb[pp * 2][1] = t[1];
                bb[pp * 2 + 1][0] = t[2]; bb[pp * 2 + 1][1] = t[3];
            }
            #pragma unroll
            for (int mf = 0; mf < 2; mf++)
                #pragma unroll
                for (int p = 0; p < 8; p++) mma_bf16(acc[mf * 8 + p], aH[mf], bb[p]);
        }
        __syncthreads();
    }

    // ---- epilogue: C += bias ----
    const int qrow = lane >> 2, qcol = (lane & 3) * 2;
    const int gmb = m0 + wm * 32;
    const int gnb = n0 + wn * 64;
    #pragma unroll
    for (int mf = 0; mf < 2; mf++) {
        int r0 = gmb + mf * 16 + qrow;
        #pragma unroll
        for (int p = 0; p < 8; p++) {
            int cn = gnb + p * 8 + qcol;
            float bx = bias[cn], by = bias[cn + 1];
            float2 v0 = make_float2(acc[mf * 8 + p][0] + bx, acc[mf * 8 + p][1] + by);
            float2 v1 = make_float2(acc[mf * 8 + p][2] + bx, acc[mf * 8 + p][3] + by);
            *(float2*)&C[(size_t)r0 * HO + cn] = v0;
            *(float2*)&C[(size_t)(r0 + 8) * HO + cn] = v1;
        }
    }
    #undef LOAD_STAGE
}

// ---------------- edge logits: per (edge, head) warp ----------------
__global__ void edge_logits_k(const int* __restrict__ src, const int* __restrict__ dst,
                              const float* __restrict__ attn_a)
{
    const int e = blockIdx.x;
    const int w = threadIdx.x >> 5, lane = threadIdx.x & 31;
    const int s = src[e], d = dst[e];
    const float* fsr = &g_fs[(size_t)s * HO + w * NH];
    const float* fdr = &g_fd[(size_t)d * HO + w * NH];
    const float* aa  = &attn_a[w * NH];
    float acc = 0.f;
    for (int i = lane; i < NH; i += 32) {
        float v = fsr[i] + fdr[i];
        v = v > 0.f ? v : 0.2f * v;
        acc = fmaf(v, aa[i], acc);
    }
    #pragma unroll
    for (int o = 16; o > 0; o >>= 1) acc += __shfl_xor_sync(0xFFFFFFFFu, acc, o);
    if (lane == 0) g_logit[(size_t)e * HEADS + w] = acc;
}

// ---------------- per-node softmax + aggregation (no atomics) ----------------
__global__ __launch_bounds__(256) void node_aggregate_k(
    const int* __restrict__ src, const int* __restrict__ dst)
{
    const int n = blockIdx.x;
    const int tid = threadIdx.x;
    __shared__ int   cnt;
    __shared__ int   eidx[EPG];
    __shared__ int   esrc[EPG];
    __shared__ float w[EPG];
    __shared__ float am[EPG];
    __shared__ float red[256];

    const int g = n / NPG;
    if (tid == 0) cnt = 0;
    __syncthreads();
    if (tid < EPG) {
        int e = g * EPG + tid;
        if (dst[e] == n) {
            int p = atomicAdd(&cnt, 1);
            eidx[p] = e;
            esrc[p] = src[e];
        }
    }
    __syncthreads();
    const int deg = cnt;

    float h0 = 0.f, h1 = 0.f, h2 = 0.f;

    if (deg > 0) {
        for (int hh = 0; hh < HEADS; hh++) {
            float lm = -1e30f;
            for (int i = tid; i < deg; i += 256)
                lm = fmaxf(lm, g_logit[(size_t)eidx[i] * HEADS + hh]);
            red[tid] = lm; __syncthreads();
            for (int s2 = 128; s2 > 0; s2 >>= 1) {
                if (tid < s2) red[tid] = fmaxf(red[tid], red[tid + s2]);
                __syncthreads();
            }
            float m = red[0]; __syncthreads();
            float ls = 0.f;
            for (int i = tid; i < deg; i += 256) {
                float ex = expf(g_logit[(size_t)eidx[i] * HEADS + hh] - m);
                w[i] = ex; ls += ex;
            }
            red[tid] = ls; __syncthreads();
            for (int s2 = 128; s2 > 0; s2 >>= 1) {
                if (tid < s2) red[tid] += red[tid + s2];
                __syncthreads();
            }
            float inv = 1.f / red[0]; __syncthreads();
            for (int i = tid; i < deg; i += 256) {
                float wi = w[i] * inv;
                w[i] = wi;
                float prev = (hh == 0) ? 0.f : am[i];
                am[i] = prev + wi * 0.125f;
            }
            __syncthreads();
            const int bh = hh * NH;
            for (int e = 0; e < deg; e++) {
                float we = w[e];
                const float* fr = &g_fs[(size_t)esrc[e] * HO + bh];
                h0 = fmaf(we, fr[tid      ], h0);
                h1 = fmaf(we, fr[tid + 256], h1);
                h2 = fmaf(we, fr[tid + 512], h2);
            }
            __syncthreads();
        }
    }
    g_h[(size_t)n * NH + tid      ] = h0 * 0.125f;
    g_h[(size_t)n * NH + tid + 256] = h1 * 0.125f;
    g_h[(size_t)n * NH + tid + 512] = h2 * 0.125f;
    for (int i = tid; i < deg; i += 256) g_amean[eidx[i]] = am[i];
}

// ---------------- attention gather to output ----------------
__global__ void attn_gather_k(const int* __restrict__ eids, float* __restrict__ out, int t)
{
    int i = blockIdx.x * 256 + threadIdx.x;
    if (i < BB * NATOM)
        out[(size_t)BB * NH + (size_t)t * BB * NATOM + i] = g_amean[eids[i]];
}

// ---------------- GRU gemms: warp per (b, j) output ----------------
__global__ void gru_gemm_k(const float* __restrict__ W_ih, const float* __restrict__ W_hh,
                           const float* __restrict__ b_ih, const float* __restrict__ b_hh,
                           const int* __restrict__ vnid)
{
    const int p = blockIdx.x * 8 + (threadIdx.x >> 5);
    const int lane = threadIdx.x & 31;
    const int b = p / H3, j = p % H3;
    const float* x  = &g_h[(size_t)vnid[b] * NH];
    const float* hp = &g_mol[(size_t)b * NH];
    const float* wi = &W_ih[(size_t)j * NH];
    const float* wh = &W_hh[(size_t)j * NH];
    float ai = 0.f, ah = 0.f;
    for (int k = lane; k < NH; k += 32) {
        ai = fmaf(x[k],  wi[k], ai);
        ah = fmaf(hp[k], wh[k], ah);
    }
    #pragma unroll
    for (int o = 16; o > 0; o >>= 1) {
        ai += __shfl_xor_sync(0xFFFFFFFFu, ai, o);
        ah += __shfl_xor_sync(0xFFFFFFFFu, ah, o);
    }
    if (lane == 0) {
        g_gi[(size_t)b * H3 + j] = ai + b_ih[j];
        g_gh[(size_t)b * H3 + j] = ah + b_hh[j];
    }
}

// ---------------- GRU combine + relu ----------------
__global__ void gru_combine_k(float* __restrict__ out_mol, int write_out)
{
    int i = blockIdx.x * 256 + threadIdx.x;
    int b = i / NH, k = i % NH;
    size_t base = (size_t)b * H3;
    float ir = g_gi[base + k], iz = g_gi[base + NH + k], in_ = g_gi[base + 2 * NH + k];
    float hr = g_gh[base + k], hz = g_gh[base + NH + k], hn  = g_gh[base + 2 * NH + k];
    float r  = 1.f / (1.f + expf(-(ir + hr)));
    float z  = 1.f / (1.f + expf(-(iz + hz)));
    float nn = tanhf(in_ + r * hn);
    float hprev = g_mol[i];
    float hnew  = (1.f - z) * nn + z * hprev;
    hnew = fmaxf(hnew, 0.f);
    g_mol[i] = hnew;
    if (write_out) out_mol[i] = hnew;
}

// ---------------- launch ----------------
extern "C" void kernel_launch(void* const* d_in, const int* in_sizes, int n_in,
                              void* d_out, int out_size)
{
    const float* h_nodes  = (const float*)d_in[0];
    const float* mol_feat = (const float*)d_in[1];
    const float* W_src    = (const float*)d_in[2];
    const float* b_src    = (const float*)d_in[3];
    const float* W_dst    = (const float*)d_in[4];
    const float* b_dst    = (const float*)d_in[5];
    const float* attn_a   = (const float*)d_in[6];
    const float* W_ih     = (const float*)d_in[7];
    const float* W_hh     = (const float*)d_in[8];
    const float* b_ih     = (const float*)d_in[9];
    const float* b_hh     = (const float*)d_in[10];
    const int*   src      = (const int*)d_in[11];
    const int*   dst      = (const int*)d_in[12];
    const int*   vnid     = (const int*)d_in[13];
    const int*   eids     = (const int*)d_in[14];
    float* out = (float*)d_out;

    cudaFuncSetAttribute(gemm_mma, cudaFuncAttributeMaxDynamicSharedMemorySize, GEMM_SMEM);

    {
        long tot = (long)NN * NH + (long)BB * NH;
        init_k<<<(int)((tot + 255) / 256), 256>>>(h_nodes, mol_feat);
    }
    {
        dim3 gr(HO / 32, NH / 32, 6);
        transpose_conv_k<<<gr, dim3(32, 8)>>>(W_src, W_dst);
    }

    __nv_bfloat16 *pBhi = nullptr, *pBlo = nullptr;
    cudaGetSymbolAddress((void**)&pBhi, g_Bhi);
    cudaGetSymbolAddress((void**)&pBlo, g_Blo);
    float* pFs = nullptr; float* pFd = nullptr;
    cudaGetSymbolAddress((void**)&pFs, g_fs);
    cudaGetSymbolAddress((void**)&pFd, g_fd);

    const long nconv = (long)NN * NH;
    for (int t = 0; t < TSTEP; t++) {
        convert_A_k<<<(int)((nconv + 255) / 256), 256>>>();
        dim3 gg(HO / 128, NN / 128);   // (48, 49)
        size_t msz = (size_t)HO * NH;
        gemm_mma<<<gg, 256, GEMM_SMEM>>>(pBhi + (size_t)(t * 2 + 0) * msz,
                                         pBlo + (size_t)(t * 2 + 0) * msz,
                                         b_src + (size_t)t * HO, pFs);
        gemm_mma<<<gg, 256, GEMM_SMEM>>>(pBhi + (size_t)(t * 2 + 1) * msz,
                                         pBlo + (size_t)(t * 2 + 1) * msz,
                                         b_dst + (size_t)t * HO, pFd);
        edge_logits_k<<<EE, 256>>>(src, dst, attn_a + (size_t)t * HEADS * NH);
        node_aggregate_k<<<NN, 256>>>(src, dst);
        attn_gather_k<<<(BB * NATOM + 255) / 256, 256>>>(eids, out, t);
        gru_gemm_k<<<BB * H3 / 8, 256>>>(W_ih + (size_t)t * H3 * NH,
                                         W_hh + (size_t)t * H3 * NH,
                                         b_ih + (size_t)t * H3,
                                         b_hh + (size_t)t * H3, vnid);
        gru_combine_k<<<BB * NH / 256, 256>>>(out, t == TSTEP - 1);
    }
}

// round 4
// speedup vs baseline: 2.0942x; 1.1446x over previous
#include <cuda_runtime.h>
#include <cuda_bf16.h>
#include <math.h>
#include <stdint.h>

// ---------------- problem constants ----------------
#define NH    768            // H
#define HEADS 8
#define HO    6144           // HEADS*H
#define TSTEP 3
#define BB    128            // molecules
#define NATOM 48
#define NPG   49             // nodes per graph
#define EPG   144            // edges per graph
#define NN    6272           // B*NPG nodes
#define EE    18432          // B*EPG edges
#define H3    2304           // 3*H

// ---------------- device scratch (no allocation allowed) ----------------
__device__ float g_h   [(size_t)NN * NH];    // current node features (fp32)
__device__ float g_fs  [(size_t)NN * HO];    // feat_src  [N, heads*H]
__device__ float g_fd  [(size_t)NN * HO];    // feat_dst  [N, heads*H]
__device__ float g_logit[(size_t)EE * HEADS];
__device__ float g_amean[(size_t)EE];
__device__ float g_mol [(size_t)BB * NH];
__device__ float g_gi  [(size_t)BB * H3];
__device__ float g_gh  [(size_t)BB * H3];

// bf16 split operands for tensor-core GEMM
__device__ __nv_bfloat16 g_Ahi[(size_t)NN * NH];
__device__ __nv_bfloat16 g_Alo[(size_t)NN * NH];
// 6 weight matrices (t*2 + sel), transposed to [N=6144, K=768]
__device__ __nv_bfloat16 g_Bhi[(size_t)6 * HO * NH];
__device__ __nv_bfloat16 g_Blo[(size_t)6 * HO * NH];

// ---------------- init: copy inputs into device state (+ bf16 split) ----------------
__global__ void init_k(const float* __restrict__ h_nodes, const float* __restrict__ mol)
{
    long i = (long)blockIdx.x * 256 + threadIdx.x;
    const long tot = (long)NN * NH;
    if (i < tot) {
        float v = h_nodes[i];
        g_h[i] = v;
        __nv_bfloat16 hi = __float2bfloat16(v);
        g_Ahi[i] = hi;
        g_Alo[i] = __float2bfloat16(v - __bfloat162float(hi));
    } else if (i < tot + (long)BB * NH) {
        g_mol[i - tot] = mol[i - tot];
    }
}

// ---------------- transpose + bf16-split all 6 weight matrices ----------------
__global__ void transpose_conv_k(const float* __restrict__ Wsrc, const float* __restrict__ Wdst)
{
    const int mat = blockIdx.z;                    // t*2 + sel
    const float* W = ((mat & 1) ? Wdst : Wsrc) + (size_t)(mat >> 1) * NH * HO;
    __shared__ float tile[32][33];
    const int n0 = blockIdx.x * 32, k0 = blockIdx.y * 32;
    const int tx = threadIdx.x, ty = threadIdx.y;  // 32 x 8
    #pragma unroll
    for (int i = ty; i < 32; i += 8)
        tile[i][tx] = W[(size_t)(k0 + i) * HO + n0 + tx];
    __syncthreads();
    const size_t base = (size_t)mat * HO * NH;
    #pragma unroll
    for (int i = ty; i < 32; i += 8) {
        float v = tile[tx][i];                      // = W[k0+tx][n0+i]
        __nv_bfloat16 hi = __float2bfloat16(v);
        __nv_bfloat16 lo = __float2bfloat16(v - __bfloat162float(hi));
        size_t o = base + (size_t)(n0 + i) * NH + k0 + tx;
        g_Bhi[o] = hi;
        g_Blo[o] = lo;
    }
}

// ================= mma.sync bf16 GEMM (base sm_103 PTX features only) ==========
// C[6272,6144] = A[6272,768] * B^T  (B stored [6144,768], K-contiguous)
// 3-term split precision, fp32 accum. Block tile 128x128, K-chunk 32,
// 3-stage cp.async pipeline, 8 warps (4m x 2n), warp tile 32m x 64n.
// gridDim.z = 2 selects (W_src -> g_fs) or (W_dst -> g_fd).

#define KC      32
#define ST_AHI  0
#define ST_ALO  8192
#define ST_BHI  16384
#define ST_BLO  24576
#define ST_SZ   32768                      // per stage
#define NSTAGE  3
#define GEMM_SMEM (NSTAGE * ST_SZ)         // 96 KB

__device__ __forceinline__ void cp16(uint32_t saddr, const void* gaddr) {
    asm volatile("cp.async.cg.shared.global [%0], [%1], 16;" :: "r"(saddr), "l"(gaddr) : "memory");
}
__device__ __forceinline__ void cp_commit() { asm volatile("cp.async.commit_group;" ::: "memory"); }
template <int N> __device__ __forceinline__ void cp_wait() {
    asm volatile("cp.async.wait_group %0;" :: "n"(N) : "memory");
}
__device__ __forceinline__ void ldsm4(uint32_t r[4], uint32_t addr) {
    asm volatile("ldmatrix.sync.aligned.m8n8.x4.shared.b16 {%0,%1,%2,%3}, [%4];"
        : "=r"(r[0]), "=r"(r[1]), "=r"(r[2]), "=r"(r[3]) : "r"(addr));
}
__device__ __forceinline__ void mma_bf16(float c[4], const uint32_t a[4], const uint32_t b[2]) {
    asm volatile("mma.sync.aligned.m16n8k16.row.col.f32.bf16.bf16.f32 "
        "{%0,%1,%2,%3}, {%4,%5,%6,%7}, {%8,%9}, {%0,%1,%2,%3};"
        : "+f"(c[0]), "+f"(c[1]), "+f"(c[2]), "+f"(c[3])
        : "r"(a[0]), "r"(a[1]), "r"(a[2]), "r"(a[3]), "r"(b[0]), "r"(b[1]));
}
__device__ __forceinline__ uint32_t smem_u32(const void* p) {
    uint32_t a;
    asm("{ .reg .u64 t; cvta.to.shared.u64 t, %1; cvt.u32.u64 %0, t; }" : "=r"(a) : "l"(p));
    return a;
}

__global__ __launch_bounds__(256, 2) void gemm_mma(
    const __nv_bfloat16* __restrict__ Bhi_base,
    const __nv_bfloat16* __restrict__ Blo_base,
    const float* __restrict__ bias_src, const float* __restrict__ bias_dst,
    float* __restrict__ Cs, float* __restrict__ Cd)
{
    extern __shared__ char sm[];
    const uint32_t sb = smem_u32(sm);
    const int tid  = threadIdx.x;
    const int wid  = tid >> 5, lane = tid & 31;
    const int m0   = blockIdx.y * 128, n0 = blockIdx.x * 128;
    const int sel  = blockIdx.z;
    const size_t msz = (size_t)HO * NH;
    const __nv_bfloat16* __restrict__ Bhi = Bhi_base + (size_t)sel * msz;
    const __nv_bfloat16* __restrict__ Blo = Blo_base + (size_t)sel * msz;
    const float* __restrict__ bias = sel ? bias_dst : bias_src;
    float* __restrict__ C = sel ? Cd : Cs;
    const int wm   = wid & 3;           // 0..3 -> 32-row slice
    const int wn   = wid >> 2;          // 0..1 -> 64-col slice

    // cp.async loader: thread -> 2 (row,seg) pairs, 4 tiles each
    const int seg0 = tid * 2;
    const int r0l  = seg0 >> 2,  c0l = seg0 & 3;
    const int r1l  = (seg0 + 1) >> 2, c1l = (seg0 + 1) & 3;
    const uint32_t so0 = r0l * 64 + ((c0l ^ (r0l & 3)) << 4);
    const uint32_t so1 = r1l * 64 + ((c1l ^ (r1l & 3)) << 4);

    #define LOAD_STAGE(stg, k0) do {                                              \
        uint32_t _b = sb + (stg) * ST_SZ;                                         \
        size_t ga0 = (size_t)(m0 + r0l) * NH + (k0) + c0l * 8;                    \
        size_t ga1 = (size_t)(m0 + r1l) * NH + (k0) + c1l * 8;                    \
        size_t gb0 = (size_t)(n0 + r0l) * NH + (k0) + c0l * 8;                    \
        size_t gb1 = (size_t)(n0 + r1l) * NH + (k0) + c1l * 8;                    \
        cp16(_b + ST_AHI + so0, g_Ahi + ga0);                                     \
        cp16(_b + ST_AHI + so1, g_Ahi + ga1);                                     \
        cp16(_b + ST_ALO + so0, g_Alo + ga0);                                     \
        cp16(_b + ST_ALO + so1, g_Alo + ga1);                                     \
        cp16(_b + ST_BHI + so0, Bhi + gb0);                                       \
        cp16(_b + ST_BHI + so1, Bhi + gb1);                                       \
        cp16(_b + ST_BLO + so0, Blo + gb0);                                       \
        cp16(_b + ST_BLO + so1, Blo + gb1);                                       \
    } while (0)

    // per-lane ldmatrix addressing
    const int sub = lane >> 3, rin = lane & 7;
    const int aRow0 = wm * 32 + (sub & 1) * 8 + rin;   // + mf*16
    const int aSegB = sub >> 1;
    const int bRow0 = wn * 64 + (sub >> 1) * 8 + rin;  // + p*16
    const int bSegB = sub & 1;

    float acc[16][4];
    #pragma unroll
    for (int i = 0; i < 16; i++)
        #pragma unroll
        for (int j = 0; j < 4; j++) acc[i][j] = 0.f;

    LOAD_STAGE(0, 0);
    cp_commit();
    LOAD_STAGE(1, KC);
    cp_commit();

    const int NCH = NH / KC;   // 24
    int stg = 0;
    for (int kc = 0; kc < NCH; kc++) {
        cp_wait<NSTAGE - 2>();
        __syncthreads();
        // safe to overwrite slot (kc-1)%NSTAGE now
        if (kc + NSTAGE - 1 < NCH) {
            LOAD_STAGE((kc + NSTAGE - 1) % NSTAGE, (kc + NSTAGE - 1) * KC);
            cp_commit();
        }

        const uint32_t stb = sb + stg * ST_SZ;
        #pragma unroll
        for (int k16 = 0; k16 < 2; k16++) {
            const int ks = k16 * 2;
            uint32_t aH[2][4], aL[2][4], bb[8][2];
            #pragma unroll
            for (int mf = 0; mf < 2; mf++) {
                int row = aRow0 + mf * 16;
                uint32_t off = row * 64 + (((ks + aSegB) ^ (row & 3)) << 4);
                ldsm4(aH[mf], stb + ST_AHI + off);
                ldsm4(aL[mf], stb + ST_ALO + off);
            }
            #pragma unroll
            for (int pp = 0; pp < 4; pp++) {
                int row = bRow0 + pp * 16;
                uint32_t off = row * 64 + (((ks + bSegB) ^ (row & 3)) << 4);
                uint32_t t[4];
                ldsm4(t, stb + ST_BHI + off);
                bb[pp * 2][0] = t[0]; bb[pp * 2][1] = t[1];
                bb[pp * 2 + 1][0] = t[2]; bb[pp * 2 + 1][1] = t[3];
            }
            #pragma unroll
            for (int mf = 0; mf < 2; mf++)
                #pragma unroll
                for (int p = 0; p < 8; p++) mma_bf16(acc[mf * 8 + p], aH[mf], bb[p]);
            #pragma unroll
            for (int mf = 0; mf < 2; mf++)
                #pragma unroll
                for (int p = 0; p < 8; p++) mma_bf16(acc[mf * 8 + p], aL[mf], bb[p]);
            #pragma unroll
            for (int pp = 0; pp < 4; pp++) {
                int row = bRow0 + pp * 16;
                uint32_t off = row * 64 + (((ks + bSegB) ^ (row & 3)) << 4);
                uint32_t t[4];
                ldsm4(t, stb + ST_BLO + off);
                bb[pp * 2][0] = t[0]; bb[pp * 2][1] = t[1];
                bb[pp * 2 + 1][0] = t[2]; bb[pp * 2 + 1][1] = t[3];
            }
            #pragma unroll
            for (int mf = 0; mf < 2; mf++)
                #pragma unroll
                for (int p = 0; p < 8; p++) mma_bf16(acc[mf * 8 + p], aH[mf], bb[p]);
        }
        stg = (stg + 1 == NSTAGE) ? 0 : stg + 1;
    }

    // epilogue: C += bias
    const int qrow = lane >> 2, qcol = (lane & 3) * 2;
    const int gmb = m0 + wm * 32;
    const int gnb = n0 + wn * 64;
    #pragma unroll
    for (int mf = 0; mf < 2; mf++) {
        int r0 = gmb + mf * 16 + qrow;
        #pragma unroll
        for (int p = 0; p < 8; p++) {
            int cn = gnb + p * 8 + qcol;
            float bx = bias[cn], by = bias[cn + 1];
            float2 v0 = make_float2(acc[mf * 8 + p][0] + bx, acc[mf * 8 + p][1] + by);
            float2 v1 = make_float2(acc[mf * 8 + p][2] + bx, acc[mf * 8 + p][3] + by);
            *(float2*)&C[(size_t)r0 * HO + cn] = v0;
            *(float2*)&C[(size_t)(r0 + 8) * HO + cn] = v1;
        }
    }
    #undef LOAD_STAGE
}

// ---------------- edge logits: per (edge, head) warp ----------------
__global__ void edge_logits_k(const int* __restrict__ src, const int* __restrict__ dst,
                              const float* __restrict__ attn_a)
{
    const int e = blockIdx.x;
    const int w = threadIdx.x >> 5, lane = threadIdx.x & 31;
    const int s = src[e], d = dst[e];
    const float* fsr = &g_fs[(size_t)s * HO + w * NH];
    const float* fdr = &g_fd[(size_t)d * HO + w * NH];
    const float* aa  = &attn_a[w * NH];
    float acc = 0.f;
    for (int i = lane; i < NH; i += 32) {
        float v = fsr[i] + fdr[i];
        v = v > 0.f ? v : 0.2f * v;
        acc = fmaf(v, aa[i], acc);
    }
    #pragma unroll
    for (int o = 16; o > 0; o >>= 1) acc += __shfl_xor_sync(0xFFFFFFFFu, acc, o);
    if (lane == 0) g_logit[(size_t)e * HEADS + w] = acc;
}

// ---------------- per-node softmax + aggregation (no atomics) ----------------
__global__ __launch_bounds__(256) void node_aggregate_k(
    const int* __restrict__ src, const int* __restrict__ dst)
{
    const int n = blockIdx.x;
    const int tid = threadIdx.x;
    __shared__ int   cnt;
    __shared__ int   eidx[EPG];
    __shared__ int   esrc[EPG];
    __shared__ float w[EPG];
    __shared__ float am[EPG];
    __shared__ float red[256];

    const int g = n / NPG;
    if (tid == 0) cnt = 0;
    __syncthreads();
    if (tid < EPG) {
        int e = g * EPG + tid;
        if (dst[e] == n) {
            int p = atomicAdd(&cnt, 1);
            eidx[p] = e;
            esrc[p] = src[e];
        }
    }
    __syncthreads();
    const int deg = cnt;

    float h0 = 0.f, h1 = 0.f, h2 = 0.f;

    if (deg > 0) {
        for (int hh = 0; hh < HEADS; hh++) {
            float lm = -1e30f;
            for (int i = tid; i < deg; i += 256)
                lm = fmaxf(lm, g_logit[(size_t)eidx[i] * HEADS + hh]);
            red[tid] = lm; __syncthreads();
            for (int s2 = 128; s2 > 0; s2 >>= 1) {
                if (tid < s2) red[tid] = fmaxf(red[tid], red[tid + s2]);
                __syncthreads();
            }
            float m = red[0]; __syncthreads();
            float ls = 0.f;
            for (int i = tid; i < deg; i += 256) {
                float ex = expf(g_logit[(size_t)eidx[i] * HEADS + hh] - m);
                w[i] = ex; ls += ex;
            }
            red[tid] = ls; __syncthreads();
            for (int s2 = 128; s2 > 0; s2 >>= 1) {
                if (tid < s2) red[tid] += red[tid + s2];
                __syncthreads();
            }
            float inv = 1.f / red[0]; __syncthreads();
            for (int i = tid; i < deg; i += 256) {
                float wi = w[i] * inv;
                w[i] = wi;
                float prev = (hh == 0) ? 0.f : am[i];
                am[i] = prev + wi * 0.125f;
            }
            __syncthreads();
            const int bh = hh * NH;
            for (int e = 0; e < deg; e++) {
                float we = w[e];
                const float* fr = &g_fs[(size_t)esrc[e] * HO + bh];
                h0 = fmaf(we, fr[tid      ], h0);
                h1 = fmaf(we, fr[tid + 256], h1);
                h2 = fmaf(we, fr[tid + 512], h2);
            }
            __syncthreads();
        }
    }
    // write h (fp32) and its bf16 hi/lo split for the next GEMM
    {
        float v;
        size_t base = (size_t)n * NH;
        __nv_bfloat16 hi;
        v = h0 * 0.125f; g_h[base + tid] = v;
        hi = __float2bfloat16(v); g_Ahi[base + tid] = hi;
        g_Alo[base + tid] = __float2bfloat16(v - __bfloat162float(hi));
        v = h1 * 0.125f; g_h[base + tid + 256] = v;
        hi = __float2bfloat16(v); g_Ahi[base + tid + 256] = hi;
        g_Alo[base + tid + 256] = __float2bfloat16(v - __bfloat162float(hi));
        v = h2 * 0.125f; g_h[base + tid + 512] = v;
        hi = __float2bfloat16(v); g_Ahi[base + tid + 512] = hi;
        g_Alo[base + tid + 512] = __float2bfloat16(v - __bfloat162float(hi));
    }
    for (int i = tid; i < deg; i += 256) g_amean[eidx[i]] = am[i];
}

// ---------------- attention gather to output ----------------
__global__ void attn_gather_k(const int* __restrict__ eids, float* __restrict__ out, int t)
{
    int i = blockIdx.x * 256 + threadIdx.x;
    if (i < BB * NATOM)
        out[(size_t)BB * NH + (size_t)t * BB * NATOM + i] = g_amean[eids[i]];
}

// ---------------- GRU gemms: warp per (b, j) output ----------------
__global__ void gru_gemm_k(const float* __restrict__ W_ih, const float* __restrict__ W_hh,
                           const float* __restrict__ b_ih, const float* __restrict__ b_hh,
                           const int* __restrict__ vnid)
{
    const int p = blockIdx.x * 8 + (threadIdx.x >> 5);
    const int lane = threadIdx.x & 31;
    const int b = p / H3, j = p % H3;
    const float* x  = &g_h[(size_t)vnid[b] * NH];
    const float* hp = &g_mol[(size_t)b * NH];
    const float* wi = &W_ih[(size_t)j * NH];
    const float* wh = &W_hh[(size_t)j * NH];
    float ai = 0.f, ah = 0.f;
    for (int k = lane; k < NH; k += 32) {
        ai = fmaf(x[k],  wi[k], ai);
        ah = fmaf(hp[k], wh[k], ah);
    }
    #pragma unroll
    for (int o = 16; o > 0; o >>= 1) {
        ai += __shfl_xor_sync(0xFFFFFFFFu, ai, o);
        ah += __shfl_xor_sync(0xFFFFFFFFu, ah, o);
    }
    if (lane == 0) {
        g_gi[(size_t)b * H3 + j] = ai + b_ih[j];
        g_gh[(size_t)b * H3 + j] = ah + b_hh[j];
    }
}

// ---------------- GRU combine + relu ----------------
__global__ void gru_combine_k(float* __restrict__ out_mol, int write_out)
{
    int i = blockIdx.x * 256 + threadIdx.x;
    int b = i / NH, k = i % NH;
    size_t base = (size_t)b * H3;
    float ir = g_gi[base + k], iz = g_gi[base + NH + k], in_ = g_gi[base + 2 * NH + k];
    float hr = g_gh[base + k], hz = g_gh[base + NH + k], hn  = g_gh[base + 2 * NH + k];
    float r  = 1.f / (1.f + expf(-(ir + hr)));
    float z  = 1.f / (1.f + expf(-(iz + hz)));
    float nn = tanhf(in_ + r * hn);
    float hprev = g_mol[i];
    float hnew  = (1.f - z) * nn + z * hprev;
    hnew = fmaxf(hnew, 0.f);
    g_mol[i] = hnew;
    if (write_out) out_mol[i] = hnew;
}

// ---------------- launch ----------------
extern "C" void kernel_launch(void* const* d_in, const int* in_sizes, int n_in,
                              void* d_out, int out_size)
{
    const float* h_nodes  = (const float*)d_in[0];
    const float* mol_feat = (const float*)d_in[1];
    const float* W_src    = (const float*)d_in[2];
    const float* b_src    = (const float*)d_in[3];
    const float* W_dst    = (const float*)d_in[4];
    const float* b_dst    = (const float*)d_in[5];
    const float* attn_a   = (const float*)d_in[6];
    const float* W_ih     = (const float*)d_in[7];
    const float* W_hh     = (const float*)d_in[8];
    const float* b_ih     = (const float*)d_in[9];
    const float* b_hh     = (const float*)d_in[10];
    const int*   src      = (const int*)d_in[11];
    const int*   dst      = (const int*)d_in[12];
    const int*   vnid     = (const int*)d_in[13];
    const int*   eids     = (const int*)d_in[14];
    float* out = (float*)d_out;

    cudaFuncSetAttribute(gemm_mma, cudaFuncAttributeMaxDynamicSharedMemorySize, GEMM_SMEM);

    {
        long tot = (long)NN * NH + (long)BB * NH;
        init_k<<<(int)((tot + 255) / 256), 256>>>(h_nodes, mol_feat);
    }
    {
        dim3 gr(HO / 32, NH / 32, 6);
        transpose_conv_k<<<gr, dim3(32, 8)>>>(W_src, W_dst);
    }

    __nv_bfloat16 *pBhi = nullptr, *pBlo = nullptr;
    cudaGetSymbolAddress((void**)&pBhi, g_Bhi);
    cudaGetSymbolAddress((void**)&pBlo, g_Blo);
    float* pFs = nullptr; float* pFd = nullptr;
    cudaGetSymbolAddress((void**)&pFs, g_fs);
    cudaGetSymbolAddress((void**)&pFd, g_fd);

    for (int t = 0; t < TSTEP; t++) {
        dim3 gg(HO / 128, NN / 128, 2);   // (48, 49, 2)
        size_t msz = (size_t)HO * NH;
        gemm_mma<<<gg, 256, GEMM_SMEM>>>(pBhi + (size_t)(t * 2) * msz,
                                         pBlo + (size_t)(t * 2) * msz,
                                         b_src + (size_t)t * HO,
                                         b_dst + (size_t)t * HO, pFs, pFd);
        edge_logits_k<<<EE, 256>>>(src, dst, attn_a + (size_t)t * HEADS * NH);
        node_aggregate_k<<<NN, 256>>>(src, dst);
        attn_gather_k<<<(BB * NATOM + 255) / 256, 256>>>(eids, out, t);
        gru_gemm_k<<<BB * H3 / 8, 256>>>(W_ih + (size_t)t * H3 * NH,
                                         W_hh + (size_t)t * H3 * NH,
                                         b_ih + (size_t)t * H3,
                                         b_hh + (size_t)t * H3, vnid);
        gru_combine_k<<<BB * NH / 256, 256>>>(out, t == TSTEP - 1);
    }
}

// round 6
// speedup vs baseline: 2.6124x; 1.2474x over previous
#include <cuda_runtime.h>
#include <cuda_bf16.h>
#include <cuda_fp16.h>
#include <math.h>
#include <stdint.h>

// ---------------- problem constants ----------------
#define NH    768            // H
#define HEADS 8
#define HO    6144           // HEADS*H
#define TSTEP 3
#define BB    128            // molecules
#define NATOM 48
#define NPG   49             // nodes per graph
#define EPG   144            // edges per graph
#define NN    6272           // B*NPG nodes
#define EE    18432          // B*EPG edges
#define H3    2304           // 3*H

// ---------------- device scratch (no allocation allowed) ----------------
__device__ float g_h   [(size_t)NN * NH];    // current node features (fp32)
__device__ float g_fs  [(size_t)NN * HO];    // feat_src  [N, heads*H]
__device__ float g_fd  [(size_t)NN * HO];    // feat_dst  [N, heads*H]
__device__ float g_logit[(size_t)EE * HEADS];
__device__ float g_amean[(size_t)EE];
__device__ float g_mol [(size_t)BB * NH];
__device__ float g_gi  [(size_t)BB * H3];
__device__ float g_gh  [(size_t)BB * H3];

// fp16 operands for tensor-core GEMM
__device__ __half g_Af [(size_t)NN * NH];            // A in fp16 (single)
// 6 weight matrices (t*2 + sel), transposed to [N=6144, K=768], fp16 hi/lo split
__device__ __half g_Bhi[(size_t)6 * HO * NH];
__device__ __half g_Blo[(size_t)6 * HO * NH];

// ---------------- init: copy inputs into device state (+ fp16) ----------------
__global__ void init_k(const float* __restrict__ h_nodes, const float* __restrict__ mol)
{
    long i = (long)blockIdx.x * 256 + threadIdx.x;
    const long tot = (long)NN * NH;
    if (i < tot) {
        float v = h_nodes[i];
        g_h[i] = v;
        g_Af[i] = __float2half_rn(v);
    } else if (i < tot + (long)BB * NH) {
        g_mol[i - tot] = mol[i - tot];
    }
}

// ---------------- transpose + fp16-split all 6 weight matrices ----------------
__global__ void transpose_conv_k(const float* __restrict__ Wsrc, const float* __restrict__ Wdst)
{
    const int mat = blockIdx.z;                    // t*2 + sel
    const float* W = ((mat & 1) ? Wdst : Wsrc) + (size_t)(mat >> 1) * NH * HO;
    __shared__ float tile[32][33];
    const int n0 = blockIdx.x * 32, k0 = blockIdx.y * 32;
    const int tx = threadIdx.x, ty = threadIdx.y;  // 32 x 8
    #pragma unroll
    for (int i = ty; i < 32; i += 8)
        tile[i][tx] = W[(size_t)(k0 + i) * HO + n0 + tx];
    __syncthreads();
    const size_t base = (size_t)mat * HO * NH;
    #pragma unroll
    for (int i = ty; i < 32; i += 8) {
        float v = tile[tx][i];                      // = W[k0+tx][n0+i]
        __half hi = __float2half_rn(v);
        __half lo = __float2half_rn(v - __half2float(hi));
        size_t o = base + (size_t)(n0 + i) * NH + k0 + tx;
        g_Bhi[o] = hi;
        g_Blo[o] = lo;
    }
}

// ================= mma.sync fp16 GEMM (base sm_103 PTX features only) ==========
// C = A * B^T, 2-pass split: Af*Bhi + Af*Blo, fp32 accum.
// Block tile 128x128, K-chunk 32, 4-stage cp.async pipeline, 8 warps (4m x 2n).
// gridDim.z = 2 selects (W_src -> g_fs) or (W_dst -> g_fd).

#define KC      32
#define ST_AF   0
#define ST_BHI  8192
#define ST_BLO  16384
#define ST_SZ   24576                      // per stage (3 tiles x 8KB)
#define NSTAGE  4
#define GEMM_SMEM (NSTAGE * ST_SZ)         // 96 KB

__device__ __forceinline__ void cp16(uint32_t saddr, const void* gaddr) {
    asm volatile("cp.async.cg.shared.global [%0], [%1], 16;" :: "r"(saddr), "l"(gaddr) : "memory");
}
__device__ __forceinline__ void cp_commit() { asm volatile("cp.async.commit_group;" ::: "memory"); }
template <int N> __device__ __forceinline__ void cp_wait() {
    asm volatile("cp.async.wait_group %0;" :: "n"(N) : "memory");
}
__device__ __forceinline__ void ldsm4(uint32_t r[4], uint32_t addr) {
    asm volatile("ldmatrix.sync.aligned.m8n8.x4.shared.b16 {%0,%1,%2,%3}, [%4];"
        : "=r"(r[0]), "=r"(r[1]), "=r"(r[2]), "=r"(r[3]) : "r"(addr));
}
__device__ __forceinline__ void mma_f16(float c[4], const uint32_t a[4], const uint32_t b[2]) {
    asm volatile("mma.sync.aligned.m16n8k16.row.col.f32.f16.f16.f32 "
        "{%0,%1,%2,%3}, {%4,%5,%6,%7}, {%8,%9}, {%0,%1,%2,%3};"
        : "+f"(c[0]), "+f"(c[1]), "+f"(c[2]), "+f"(c[3])
        : "r"(a[0]), "r"(a[1]), "r"(a[2]), "r"(a[3]), "r"(b[0]), "r"(b[1]));
}
__device__ __forceinline__ uint32_t smem_u32(const void* p) {
    uint32_t a;
    asm("{ .reg .u64 t; cvta.to.shared.u64 t, %1; cvt.u32.u64 %0, t; }" : "=r"(a) : "l"(p));
    return a;
}

__global__ __launch_bounds__(256, 2) void gemm_mma(
    const __half* __restrict__ Bhi_base,
    const __half* __restrict__ Blo_base,
    const float* __restrict__ bias_src, const float* __restrict__ bias_dst,
    float* __restrict__ Cs, float* __restrict__ Cd)
{
    extern __shared__ char sm[];
    const uint32_t sb = smem_u32(sm);
    const int tid  = threadIdx.x;
    const int wid  = tid >> 5, lane = tid & 31;
    const int m0   = blockIdx.y * 128, n0 = blockIdx.x * 128;
    const int sel  = blockIdx.z;
    const size_t msz = (size_t)HO * NH;
    const __half* __restrict__ Bhi = Bhi_base + (size_t)sel * msz;
    const __half* __restrict__ Blo = Blo_base + (size_t)sel * msz;
    const float* __restrict__ bias = sel ? bias_dst : bias_src;
    float* __restrict__ C = sel ? Cd : Cs;
    const int wm   = wid & 3;           // 0..3 -> 32-row slice
    const int wn   = wid >> 2;          // 0..1 -> 64-col slice

    // cp.async loader: thread -> 2 (row,seg) pairs, 3 tiles each
    const int seg0 = tid * 2;
    const int r0l  = seg0 >> 2,  c0l = seg0 & 3;
    const int r1l  = (seg0 + 1) >> 2, c1l = (seg0 + 1) & 3;
    const uint32_t so0 = r0l * 64 + ((c0l ^ (r0l & 3)) << 4);
    const uint32_t so1 = r1l * 64 + ((c1l ^ (r1l & 3)) << 4);

    #define LOAD_STAGE(stg, k0) do {                                              \
        uint32_t _b = sb + (stg) * ST_SZ;                                         \
        size_t ga0 = (size_t)(m0 + r0l) * NH + (k0) + c0l * 8;                    \
        size_t ga1 = (size_t)(m0 + r1l) * NH + (k0) + c1l * 8;                    \
        size_t gb0 = (size_t)(n0 + r0l) * NH + (k0) + c0l * 8;                    \
        size_t gb1 = (size_t)(n0 + r1l) * NH + (k0) + c1l * 8;                    \
        cp16(_b + ST_AF  + so0, g_Af + ga0);                                      \
        cp16(_b + ST_AF  + so1, g_Af + ga1);                                      \
        cp16(_b + ST_BHI + so0, Bhi + gb0);                                       \
        cp16(_b + ST_BHI + so1, Bhi + gb1);                                       \
        cp16(_b + ST_BLO + so0, Blo + gb0);                                       \
        cp16(_b + ST_BLO + so1, Blo + gb1);                                       \
    } while (0)

    // per-lane ldmatrix addressing
    const int sub = lane >> 3, rin = lane & 7;
    const int aRow0 = wm * 32 + (sub & 1) * 8 + rin;   // + mf*16
    const int aSegB = sub >> 1;
    const int bRow0 = wn * 64 + (sub >> 1) * 8 + rin;  // + p*16
    const int bSegB = sub & 1;

    float acc[16][4];
    #pragma unroll
    for (int i = 0; i < 16; i++)
        #pragma unroll
        for (int j = 0; j < 4; j++) acc[i][j] = 0.f;

    LOAD_STAGE(0, 0);      cp_commit();
    LOAD_STAGE(1, KC);     cp_commit();
    LOAD_STAGE(2, 2 * KC); cp_commit();

    const int NCH = NH / KC;   // 24
    int stg = 0;
    for (int kc = 0; kc < NCH; kc++) {
        cp_wait<NSTAGE - 2>();
        __syncthreads();
        // slot (kc + NSTAGE - 1) % NSTAGE == (kc-1)%NSTAGE, safe after the sync
        if (kc + NSTAGE - 1 < NCH) {
            LOAD_STAGE((kc + NSTAGE - 1) % NSTAGE, (kc + NSTAGE - 1) * KC);
            cp_commit();
        } else {
            cp_commit();   // keep group count uniform so cp_wait<2> semantics hold
        }

        const uint32_t stb = sb + stg * ST_SZ;
        #pragma unroll
        for (int k16 = 0; k16 < 2; k16++) {
            const int ks = k16 * 2;
            uint32_t aF[2][4], bb[8][2];
            #pragma unroll
            for (int mf = 0; mf < 2; mf++) {
                int row = aRow0 + mf * 16;
                uint32_t off = row * 64 + (((ks + aSegB) ^ (row & 3)) << 4);
                ldsm4(aF[mf], stb + ST_AF + off);
            }
            #pragma unroll
            for (int pp = 0; pp < 4; pp++) {
                int row = bRow0 + pp * 16;
                uint32_t off = row * 64 + (((ks + bSegB) ^ (row & 3)) << 4);
                uint32_t t[4];
                ldsm4(t, stb + ST_BHI + off);
                bb[pp * 2][0] = t[0]; bb[pp * 2][1] = t[1];
                bb[pp * 2 + 1][0] = t[2]; bb[pp * 2 + 1][1] = t[3];
            }
            #pragma unroll
            for (int mf = 0; mf < 2; mf++)
                #pragma unroll
                for (int p = 0; p < 8; p++) mma_f16(acc[mf * 8 + p], aF[mf], bb[p]);
            #pragma unroll
            for (int pp = 0; pp < 4; pp++) {
                int row = bRow0 + pp * 16;
                uint32_t off = row * 64 + (((ks + bSegB) ^ (row & 3)) << 4);
                uint32_t t[4];
                ldsm4(t, stb + ST_BLO + off);
                bb[pp * 2][0] = t[0]; bb[pp * 2][1] = t[1];
                bb[pp * 2 + 1][0] = t[2]; bb[pp * 2 + 1][1] = t[3];
            }
            #pragma unroll
            for (int mf = 0; mf < 2; mf++)
                #pragma unroll
                for (int p = 0; p < 8; p++) mma_f16(acc[mf * 8 + p], aF[mf], bb[p]);
        }
        stg = (stg + 1 == NSTAGE) ? 0 : stg + 1;
    }

    // epilogue: C += bias
    const int qrow = lane >> 2, qcol = (lane & 3) * 2;
    const int gmb = m0 + wm * 32;
    const int gnb = n0 + wn * 64;
    #pragma unroll
    for (int mf = 0; mf < 2; mf++) {
        int r0 = gmb + mf * 16 + qrow;
        #pragma unroll
        for (int p = 0; p < 8; p++) {
            int cn = gnb + p * 8 + qcol;
            float bx = bias[cn], by = bias[cn + 1];
            float2 v0 = make_float2(acc[mf * 8 + p][0] + bx, acc[mf * 8 + p][1] + by);
            float2 v1 = make_float2(acc[mf * 8 + p][2] + bx, acc[mf * 8 + p][3] + by);
            *(float2*)&C[(size_t)r0 * HO + cn] = v0;
            *(float2*)&C[(size_t)(r0 + 8) * HO + cn] = v1;
        }
    }
    #undef LOAD_STAGE
}

// ---------------- edge logits: per (edge, head) warp ----------------
__global__ void edge_logits_k(const int* __restrict__ src, const int* __restrict__ dst,
                              const float* __restrict__ attn_a)
{
    const int e = blockIdx.x;
    const int w = threadIdx.x >> 5, lane = threadIdx.x & 31;
    const int s = src[e], d = dst[e];
    const float* fsr = &g_fs[(size_t)s * HO + w * NH];
    const float* fdr = &g_fd[(size_t)d * HO + w * NH];
    const float* aa  = &attn_a[w * NH];
    float acc = 0.f;
    for (int i = lane; i < NH; i += 32) {
        float v = fsr[i] + fdr[i];
        v = v > 0.f ? v : 0.2f * v;
        acc = fmaf(v, aa[i], acc);
    }
    #pragma unroll
    for (int o = 16; o > 0; o >>= 1) acc += __shfl_xor_sync(0xFFFFFFFFu, acc, o);
    if (lane == 0) g_logit[(size_t)e * HEADS + w] = acc;
}

// ---------------- per-node softmax + aggregation (no atomics) ----------------
__global__ __launch_bounds__(256) void node_aggregate_k(
    const int* __restrict__ src, const int* __restrict__ dst)
{
    const int n = blockIdx.x;
    const int tid = threadIdx.x;
    __shared__ int   cnt;
    __shared__ int   eidx[EPG];
    __shared__ int   esrc[EPG];
    __shared__ float w[EPG];
    __shared__ float am[EPG];
    __shared__ float red[256];

    const int g = n / NPG;
    if (tid == 0) cnt = 0;
    __syncthreads();
    if (tid < EPG) {
        int e = g * EPG + tid;
        if (dst[e] == n) {
            int p = atomicAdd(&cnt, 1);
            eidx[p] = e;
            esrc[p] = src[e];
        }
    }
    __syncthreads();
    const int deg = cnt;

    float h0 = 0.f, h1 = 0.f, h2 = 0.f;

    if (deg > 0) {
        for (int hh = 0; hh < HEADS; hh++) {
            float lm = -1e30f;
            for (int i = tid; i < deg; i += 256)
                lm = fmaxf(lm, g_logit[(size_t)eidx[i] * HEADS + hh]);
            red[tid] = lm; __syncthreads();
            for (int s2 = 128; s2 > 0; s2 >>= 1) {
                if (tid < s2) red[tid] = fmaxf(red[tid], red[tid + s2]);
                __syncthreads();
            }
            float m = red[0]; __syncthreads();
            float ls = 0.f;
            for (int i = tid; i < deg; i += 256) {
                float ex = expf(g_logit[(size_t)eidx[i] * HEADS + hh] - m);
                w[i] = ex; ls += ex;
            }
            red[tid] = ls; __syncthreads();
            for (int s2 = 128; s2 > 0; s2 >>= 1) {
                if (tid < s2) red[tid] += red[tid + s2];
                __syncthreads();
            }
            float inv = 1.f / red[0]; __syncthreads();
            for (int i = tid; i < deg; i += 256) {
                float wi = w[i] * inv;
                w[i] = wi;
                float prev = (hh == 0) ? 0.f : am[i];
                am[i] = prev + wi * 0.125f;
            }
            __syncthreads();
            const int bh = hh * NH;
            for (int e = 0; e < deg; e++) {
                float we = w[e];
                const float* fr = &g_fs[(size_t)esrc[e] * HO + bh];
                h0 = fmaf(we, fr[tid      ], h0);
                h1 = fmaf(we, fr[tid + 256], h1);
                h2 = fmaf(we, fr[tid + 512], h2);
            }
            __syncthreads();
        }
    }
    // write h (fp32) and its fp16 image for the next GEMM
    {
        size_t base = (size_t)n * NH;
        float v;
        v = h0 * 0.125f; g_h[base + tid]       = v; g_Af[base + tid]       = __float2half_rn(v);
        v = h1 * 0.125f; g_h[base + tid + 256] = v; g_Af[base + tid + 256] = __float2half_rn(v);
        v = h2 * 0.125f; g_h[base + tid + 512] = v; g_Af[base + tid + 512] = __float2half_rn(v);
    }
    for (int i = tid; i < deg; i += 256) g_amean[eidx[i]] = am[i];
}

// ---------------- attention gather to output ----------------
__global__ void attn_gather_k(const int* __restrict__ eids, float* __restrict__ out, int t)
{
    int i = blockIdx.x * 256 + threadIdx.x;
    if (i < BB * NATOM)
        out[(size_t)BB * NH + (size_t)t * BB * NATOM + i] = g_amean[eids[i]];
}

// ---------------- GRU gemms: warp per (b, j) output ----------------
__global__ void gru_gemm_k(const float* __restrict__ W_ih, const float* __restrict__ W_hh,
                           const float* __restrict__ b_ih, const float* __restrict__ b_hh,
                           const int* __restrict__ vnid)
{
    const int p = blockIdx.x * 8 + (threadIdx.x >> 5);
    const int lane = threadIdx.x & 31;
    const int b = p / H3, j = p % H3;
    const float* x  = &g_h[(size_t)vnid[b] * NH];
    const float* hp = &g_mol[(size_t)b * NH];
    const float* wi = &W_ih[(size_t)j * NH];
    const float* wh = &W_hh[(size_t)j * NH];
    float ai = 0.f, ah = 0.f;
    for (int k = lane; k < NH; k += 32) {
        ai = fmaf(x[k],  wi[k], ai);
        ah = fmaf(hp[k], wh[k], ah);
    }
    #pragma unroll
    for (int o = 16; o > 0; o >>= 1) {
        ai += __shfl_xor_sync(0xFFFFFFFFu, ai, o);
        ah += __shfl_xor_sync(0xFFFFFFFFu, ah, o);
    }
    if (lane == 0) {
        g_gi[(size_t)b * H3 + j] = ai + b_ih[j];
        g_gh[(size_t)b * H3 + j] = ah + b_hh[j];
    }
}

// ---------------- GRU combine + relu ----------------
__global__ void gru_combine_k(float* __restrict__ out_mol, int write_out)
{
    int i = blockIdx.x * 256 + threadIdx.x;
    int b = i / NH, k = i % NH;
    size_t base = (size_t)b * H3;
    float ir = g_gi[base + k], iz = g_gi[base + NH + k], in_ = g_gi[base + 2 * NH + k];
    float hr = g_gh[base + k], hz = g_gh[base + NH + k], hn  = g_gh[base + 2 * NH + k];
    float r  = 1.f / (1.f + expf(-(ir + hr)));
    float z  = 1.f / (1.f + expf(-(iz + hz)));
    float nn = tanhf(in_ + r * hn);
    float hprev = g_mol[i];
    float hnew  = (1.f - z) * nn + z * hprev;
    hnew = fmaxf(hnew, 0.f);
    g_mol[i] = hnew;
    if (write_out) out_mol[i] = hnew;
}

// ---------------- launch ----------------
extern "C" void kernel_launch(void* const* d_in, const int* in_sizes, int n_in,
                              void* d_out, int out_size)
{
    const float* h_nodes  = (const float*)d_in[0];
    const float* mol_feat = (const float*)d_in[1];
    const float* W_src    = (const float*)d_in[2];
    const float* b_src    = (const float*)d_in[3];
    const float* W_dst    = (const float*)d_in[4];
    const float* b_dst    = (const float*)d_in[5];
    const float* attn_a   = (const float*)d_in[6];
    const float* W_ih     = (const float*)d_in[7];
    const float* W_hh     = (const float*)d_in[8];
    const float* b_ih     = (const float*)d_in[9];
    const float* b_hh     = (const float*)d_in[10];
    const int*   src      = (const int*)d_in[11];
    const int*   dst      = (const int*)d_in[12];
    const int*   vnid     = (const int*)d_in[13];
    const int*   eids     = (const int*)d_in[14];
    float* out = (float*)d_out;

    cudaFuncSetAttribute(gemm_mma, cudaFuncAttributeMaxDynamicSharedMemorySize, GEMM_SMEM);

    {
        long tot = (long)NN * NH + (long)BB * NH;
        init_k<<<(int)((tot + 255) / 256), 256>>>(h_nodes, mol_feat);
    }
    {
        dim3 gr(HO / 32, NH / 32, 6);
        transpose_conv_k<<<gr, dim3(32, 8)>>>(W_src, W_dst);
    }

    __half *pBhi = nullptr, *pBlo = nullptr;
    cudaGetSymbolAddress((void**)&pBhi, g_Bhi);
    cudaGetSymbolAddress((void**)&pBlo, g_Blo);
    float* pFs = nullptr; float* pFd = nullptr;
    cudaGetSymbolAddress((void**)&pFs, g_fs);
    cudaGetSymbolAddress((void**)&pFd, g_fd);

    for (int t = 0; t < TSTEP; t++) {
        dim3 gg(HO / 128, NN / 128, 2);   // (48, 49, 2)
        size_t msz = (size_t)HO * NH;
        gemm_mma<<<gg, 256, GEMM_SMEM>>>(pBhi + (size_t)(t * 2) * msz,
                                         pBlo + (size_t)(t * 2) * msz,
                                         b_src + (size_t)t * HO,
                                         b_dst + (size_t)t * HO, pFs, pFd);
        edge_logits_k<<<EE, 256>>>(src, dst, attn_a + (size_t)t * HEADS * NH);
        node_aggregate_k<<<NN, 256>>>(src, dst);
        attn_gather_k<<<(BB * NATOM + 255) / 256, 256>>>(eids, out, t);
        gru_gemm_k<<<BB * H3 / 8, 256>>>(W_ih + (size_t)t * H3 * NH,
                                         W_hh + (size_t)t * H3 * NH,
                                         b_ih + (size_t)t * H3,
                                         b_hh + (size_t)t * H3, vnid);
        gru_combine_k<<<BB * NH / 256, 256>>>(out, t == TSTEP - 1);
    }
}

// round 8
// speedup vs baseline: 3.2784x; 1.2550x over previous
#include <cuda_runtime.h>
#include <cuda_bf16.h>
#include <cuda_fp16.h>
#include <math.h>
#include <stdint.h>

// ---------------- problem constants ----------------
#define NH    768            // H
#define HEADS 8
#define HO    6144           // HEADS*H
#define TSTEP 3
#define BB    128            // molecules
#define NATOM 48
#define NPG   49             // nodes per graph
#define EPG   144            // edges per graph
#define NN    6272           // B*NPG nodes
#define EE    18432          // B*EPG edges
#define H3    2304           // 3*H

// ---------------- device scratch (no allocation allowed) ----------------
__device__ float  g_h   [(size_t)NN * NH];    // current node features (fp32)
__device__ __half g_fsh [(size_t)NN * HO];    // feat_src  [N, heads*H] fp16
__device__ __half g_fdh [(size_t)NN * HO];    // feat_dst  [N, heads*H] fp16
__device__ float  g_logit[(size_t)EE * HEADS];
__device__ float  g_amean[(size_t)EE];
__device__ float  g_mol [(size_t)BB * NH];
__device__ float  g_gi  [(size_t)BB * H3];
__device__ float  g_gh  [(size_t)BB * H3];

// fp16 operands for tensor-core GEMM
__device__ __half g_Af [(size_t)NN * NH];     // A in fp16
// 6 weight matrices (t*2 + sel), transposed to [N=6144, K=768], fp16
__device__ __half g_Bf [(size_t)6 * HO * NH];

// ---------------- init: copy inputs into device state (+ fp16) ----------------
__global__ void init_k(const float* __restrict__ h_nodes, const float* __restrict__ mol)
{
    long i = (long)blockIdx.x * 256 + threadIdx.x;
    const long tot = (long)NN * NH;
    if (i < tot) {
        float v = h_nodes[i];
        g_h[i] = v;
        g_Af[i] = __float2half_rn(v);
    } else if (i < tot + (long)BB * NH) {
        g_mol[i - tot] = mol[i - tot];
    }
}

// ---------------- transpose + fp16-convert all 6 weight matrices ----------------
__global__ void transpose_conv_k(const float* __restrict__ Wsrc, const float* __restrict__ Wdst)
{
    const int mat = blockIdx.z;                    // t*2 + sel
    const float* W = ((mat & 1) ? Wdst : Wsrc) + (size_t)(mat >> 1) * NH * HO;
    __shared__ float tile[32][33];
    const int n0 = blockIdx.x * 32, k0 = blockIdx.y * 32;
    const int tx = threadIdx.x, ty = threadIdx.y;  // 32 x 8
    #pragma unroll
    for (int i = ty; i < 32; i += 8)
        tile[i][tx] = W[(size_t)(k0 + i) * HO + n0 + tx];
    __syncthreads();
    const size_t base = (size_t)mat * HO * NH;
    #pragma unroll
    for (int i = ty; i < 32; i += 8)
        g_Bf[base + (size_t)(n0 + i) * NH + k0 + tx] = __float2half_rn(tile[tx][i]);
}

// ================= mma.sync fp16 GEMM (base sm_103 PTX features only) ==========
// C = A * B^T, single-pass fp16, fp32 accum. Block tile 128x128, K-chunk 32,
// 6-stage cp.async pipeline, 8 warps (4m x 2n). gridDim.z selects fs/fd.

#define KC      32
#define ST_AF   0
#define ST_BF   8192
#define ST_SZ   16384                      // per stage (2 tiles x 8KB)
#define NSTAGE  6
#define GEMM_SMEM (NSTAGE * ST_SZ)         // 96 KB

__device__ __forceinline__ void cp16(uint32_t saddr, const void* gaddr) {
    asm volatile("cp.async.cg.shared.global [%0], [%1], 16;" :: "r"(saddr), "l"(gaddr) : "memory");
}
__device__ __forceinline__ void cp_commit() { asm volatile("cp.async.commit_group;" ::: "memory"); }
template <int N> __device__ __forceinline__ void cp_wait() {
    asm volatile("cp.async.wait_group %0;" :: "n"(N) : "memory");
}
__device__ __forceinline__ void ldsm4(uint32_t r[4], uint32_t addr) {
    asm volatile("ldmatrix.sync.aligned.m8n8.x4.shared.b16 {%0,%1,%2,%3}, [%4];"
        : "=r"(r[0]), "=r"(r[1]), "=r"(r[2]), "=r"(r[3]) : "r"(addr));
}
__device__ __forceinline__ void mma_f16(float c[4], const uint32_t a[4], const uint32_t b[2]) {
    asm volatile("mma.sync.aligned.m16n8k16.row.col.f32.f16.f16.f32 "
        "{%0,%1,%2,%3}, {%4,%5,%6,%7}, {%8,%9}, {%0,%1,%2,%3};"
        : "+f"(c[0]), "+f"(c[1]), "+f"(c[2]), "+f"(c[3])
        : "r"(a[0]), "r"(a[1]), "r"(a[2]), "r"(a[3]), "r"(b[0]), "r"(b[1]));
}
__device__ __forceinline__ uint32_t smem_u32(const void* p) {
    uint32_t a;
    asm("{ .reg .u64 t; cvta.to.shared.u64 t, %1; cvt.u32.u64 %0, t; }" : "=r"(a) : "l"(p));
    return a;
}

__global__ __launch_bounds__(256, 2) void gemm_mma(
    const __half* __restrict__ Bf_base,
    const float* __restrict__ bias_src, const float* __restrict__ bias_dst)
{
    extern __shared__ char sm[];
    const uint32_t sb = smem_u32(sm);
    const int tid  = threadIdx.x;
    const int wid  = tid >> 5, lane = tid & 31;
    const int m0   = blockIdx.y * 128, n0 = blockIdx.x * 128;
    const int sel  = blockIdx.z;
    const size_t msz = (size_t)HO * NH;
    const __half* __restrict__ Bf = Bf_base + (size_t)sel * msz;
    const float* __restrict__ bias = sel ? bias_dst : bias_src;
    __half* __restrict__ C = sel ? g_fdh : g_fsh;
    const int wm   = wid & 3;           // 0..3 -> 32-row slice
    const int wn   = wid >> 2;          // 0..1 -> 64-col slice

    // cp.async loader: thread -> 2 (row,seg) pairs, 2 tiles each
    const int seg0 = tid * 2;
    const int r0l  = seg0 >> 2,  c0l = seg0 & 3;
    const int r1l  = (seg0 + 1) >> 2, c1l = (seg0 + 1) & 3;
    const uint32_t so0 = r0l * 64 + ((c0l ^ (r0l & 3)) << 4);
    const uint32_t so1 = r1l * 64 + ((c1l ^ (r1l & 3)) << 4);

    #define LOAD_STAGE(stg, k0) do {                                              \
        uint32_t _b = sb + (stg) * ST_SZ;                                         \
        size_t ga0 = (size_t)(m0 + r0l) * NH + (k0) + c0l * 8;                    \
        size_t ga1 = (size_t)(m0 + r1l) * NH + (k0) + c1l * 8;                    \
        size_t gb0 = (size_t)(n0 + r0l) * NH + (k0) + c0l * 8;                    \
        size_t gb1 = (size_t)(n0 + r1l) * NH + (k0) + c1l * 8;                    \
        cp16(_b + ST_AF + so0, g_Af + ga0);                                       \
        cp16(_b + ST_AF + so1, g_Af + ga1);                                       \
        cp16(_b + ST_BF + so0, Bf + gb0);                                         \
        cp16(_b + ST_BF + so1, Bf + gb1);                                         \
    } while (0)

    // per-lane ldmatrix addressing
    const int sub = lane >> 3, rin = lane & 7;
    const int aRow0 = wm * 32 + (sub & 1) * 8 + rin;   // + mf*16
    const int aSegB = sub >> 1;
    const int bRow0 = wn * 64 + (sub >> 1) * 8 + rin;  // + p*16
    const int bSegB = sub & 1;

    float acc[16][4];
    #pragma unroll
    for (int i = 0; i < 16; i++)
        #pragma unroll
        for (int j = 0; j < 4; j++) acc[i][j] = 0.f;

    #pragma unroll
    for (int s = 0; s < NSTAGE - 1; s++) {
        LOAD_STAGE(s, s * KC);
        cp_commit();
    }

    const int NCH = NH / KC;   // 24
    int stg = 0;
    for (int kc = 0; kc < NCH; kc++) {
        cp_wait<NSTAGE - 2>();
        __syncthreads();
        if (kc + NSTAGE - 1 < NCH) {
            LOAD_STAGE((kc + NSTAGE - 1) % NSTAGE, (kc + NSTAGE - 1) * KC);
        }
        cp_commit();   // uniform group counting

        const uint32_t stb = sb + stg * ST_SZ;
        #pragma unroll
        for (int k16 = 0; k16 < 2; k16++) {
            const int ks = k16 * 2;
            uint32_t aF[2][4], bb[8][2];
            #pragma unroll
            for (int mf = 0; mf < 2; mf++) {
                int row = aRow0 + mf * 16;
                uint32_t off = row * 64 + (((ks + aSegB) ^ (row & 3)) << 4);
                ldsm4(aF[mf], stb + ST_AF + off);
            }
            #pragma unroll
            for (int pp = 0; pp < 4; pp++) {
                int row = bRow0 + pp * 16;
                uint32_t off = row * 64 + (((ks + bSegB) ^ (row & 3)) << 4);
                uint32_t t[4];
                ldsm4(t, stb + ST_BF + off);
                bb[pp * 2][0] = t[0]; bb[pp * 2][1] = t[1];
                bb[pp * 2 + 1][0] = t[2]; bb[pp * 2 + 1][1] = t[3];
            }
            #pragma unroll
            for (int mf = 0; mf < 2; mf++)
                #pragma unroll
                for (int p = 0; p < 8; p++) mma_f16(acc[mf * 8 + p], aF[mf], bb[p]);
        }
        stg = (stg + 1 == NSTAGE) ? 0 : stg + 1;
    }

    // epilogue: C = fp16(acc + bias)
    const int qrow = lane >> 2, qcol = (lane & 3) * 2;
    const int gmb = m0 + wm * 32;
    const int gnb = n0 + wn * 64;
    #pragma unroll
    for (int mf = 0; mf < 2; mf++) {
        int r0 = gmb + mf * 16 + qrow;
        #pragma unroll
        for (int p = 0; p < 8; p++) {
            int cn = gnb + p * 8 + qcol;
            float bx = bias[cn], by = bias[cn + 1];
            __half2 v0 = __floats2half2_rn(acc[mf * 8 + p][0] + bx, acc[mf * 8 + p][1] + by);
            __half2 v1 = __floats2half2_rn(acc[mf * 8 + p][2] + bx, acc[mf * 8 + p][3] + by);
            *(__half2*)&C[(size_t)r0 * HO + cn] = v0;
            *(__half2*)&C[(size_t)(r0 + 8) * HO + cn] = v1;
        }
    }
    #undef LOAD_STAGE
}

// ---------------- edge logits: per (edge, head) warp, fp16 reads ----------------
__global__ void edge_logits_k(const int* __restrict__ src, const int* __restrict__ dst,
                              const float* __restrict__ attn_a)
{
    const int e = blockIdx.x;
    const int w = threadIdx.x >> 5, lane = threadIdx.x & 31;
    const int s = src[e], d = dst[e];
    const __half* fsr = &g_fsh[(size_t)s * HO + w * NH];
    const __half* fdr = &g_fdh[(size_t)d * HO + w * NH];
    const float* aa  = &attn_a[w * NH];
    float acc = 0.f;
    for (int i = lane * 2; i < NH; i += 64) {
        float2 a2 = __half22float2(*(const __half2*)&fsr[i]);
        float2 d2 = __half22float2(*(const __half2*)&fdr[i]);
        float v0 = a2.x + d2.x; v0 = v0 > 0.f ? v0 : 0.2f * v0;
        float v1 = a2.y + d2.y; v1 = v1 > 0.f ? v1 : 0.2f * v1;
        acc = fmaf(v0, aa[i], acc);
        acc = fmaf(v1, aa[i + 1], acc);
    }
    #pragma unroll
    for (int o = 16; o > 0; o >>= 1) acc += __shfl_xor_sync(0xFFFFFFFFu, acc, o);
    if (lane == 0) g_logit[(size_t)e * HEADS + w] = acc;
}

// ---------------- per-node softmax + aggregation (no atomics) ----------------
__global__ __launch_bounds__(256) void node_aggregate_k(
    const int* __restrict__ src, const int* __restrict__ dst)
{
    const int n = blockIdx.x;
    const int tid = threadIdx.x;
    __shared__ int   cnt;
    __shared__ int   eidx[EPG];
    __shared__ int   esrc[EPG];
    __shared__ float w[EPG];
    __shared__ float am[EPG];
    __shared__ float red[256];

    const int g = n / NPG;
    if (tid == 0) cnt = 0;
    __syncthreads();
    if (tid < EPG) {
        int e = g * EPG + tid;
        if (dst[e] == n) {
            int p = atomicAdd(&cnt, 1);
            eidx[p] = e;
            esrc[p] = src[e];
        }
    }
    __syncthreads();
    const int deg = cnt;

    float h0 = 0.f, h1 = 0.f, h2 = 0.f;

    if (deg > 0) {
        for (int hh = 0; hh < HEADS; hh++) {
            float lm = -1e30f;
            for (int i = tid; i < deg; i += 256)
                lm = fmaxf(lm, g_logit[(size_t)eidx[i] * HEADS + hh]);
            red[tid] = lm; __syncthreads();
            for (int s2 = 128; s2 > 0; s2 >>= 1) {
                if (tid < s2) red[tid] = fmaxf(red[tid], red[tid + s2]);
                __syncthreads();
            }
            float m = red[0]; __syncthreads();
            float ls = 0.f;
            for (int i = tid; i < deg; i += 256) {
                float ex = expf(g_logit[(size_t)eidx[i] * HEADS + hh] - m);
                w[i] = ex; ls += ex;
            }
            red[tid] = ls; __syncthreads();
            for (int s2 = 128; s2 > 0; s2 >>= 1) {
                if (tid < s2) red[tid] += red[tid + s2];
                __syncthreads();
            }
            float inv = 1.f / red[0]; __syncthreads();
            for (int i = tid; i < deg; i += 256) {
                float wi = w[i] * inv;
                w[i] = wi;
                float prev = (hh == 0) ? 0.f : am[i];
                am[i] = prev + wi * 0.125f;
            }
            __syncthreads();
            const int bh = hh * NH;
            for (int e = 0; e < deg; e++) {
                float we = w[e];
                const __half* fr = &g_fsh[(size_t)esrc[e] * HO + bh];
                h0 = fmaf(we, __half2float(fr[tid      ]), h0);
                h1 = fmaf(we, __half2float(fr[tid + 256]), h1);
                h2 = fmaf(we, __half2float(fr[tid + 512]), h2);
            }
            __syncthreads();
        }
    }
    // write h (fp32) and its fp16 image for the next GEMM
    {
        size_t base = (size_t)n * NH;
        float v;
        v = h0 * 0.125f; g_h[base + tid]       = v; g_Af[base + tid]       = __float2half_rn(v);
        v = h1 * 0.125f; g_h[base + tid + 256] = v; g_Af[base + tid + 256] = __float2half_rn(v);
        v = h2 * 0.125f; g_h[base + tid + 512] = v; g_Af[base + tid + 512] = __float2half_rn(v);
    }
    for (int i = tid; i < deg; i += 256) g_amean[eidx[i]] = am[i];
}

// ---------------- attention gather to output ----------------
__global__ void attn_gather_k(const int* __restrict__ eids, float* __restrict__ out, int t)
{
    int i = blockIdx.x * 256 + threadIdx.x;
    if (i < BB * NATOM)
        out[(size_t)BB * NH + (size_t)t * BB * NATOM + i] = g_amean[eids[i]];
}

// ---------------- GRU gemms: warp per (b, j) output ----------------
__global__ void gru_gemm_k(const float* __restrict__ W_ih, const float* __restrict__ W_hh,
                           const float* __restrict__ b_ih, const float* __restrict__ b_hh,
                           const int* __restrict__ vnid)
{
    const int p = blockIdx.x * 8 + (threadIdx.x >> 5);
    const int lane = threadIdx.x & 31;
    const int b = p / H3, j = p % H3;
    const float* x  = &g_h[(size_t)vnid[b] * NH];
    const float* hp = &g_mol[(size_t)b * NH];
    const float* wi = &W_ih[(size_t)j * NH];
    const float* wh = &W_hh[(size_t)j * NH];
    float ai = 0.f, ah = 0.f;
    for (int k = lane; k < NH; k += 32) {
        ai = fmaf(x[k],  wi[k], ai);
        ah = fmaf(hp[k], wh[k], ah);
    }
    #pragma unroll
    for (int o = 16; o > 0; o >>= 1) {
        ai += __shfl_xor_sync(0xFFFFFFFFu, ai, o);
        ah += __shfl_xor_sync(0xFFFFFFFFu, ah, o);
    }
    if (lane == 0) {
        g_gi[(size_t)b * H3 + j] = ai + b_ih[j];
        g_gh[(size_t)b * H3 + j] = ah + b_hh[j];
    }
}

// ---------------- GRU combine + relu ----------------
__global__ void gru_combine_k(float* __restrict__ out_mol, int write_out)
{
    int i = blockIdx.x * 256 + threadIdx.x;
    int b = i / NH, k = i % NH;
    size_t base = (size_t)b * H3;
    float ir = g_gi[base + k], iz = g_gi[base + NH + k], in_ = g_gi[base + 2 * NH + k];
    float hr = g_gh[base + k], hz = g_gh[base + NH + k], hn  = g_gh[base + 2 * NH + k];
    float r  = 1.f / (1.f + expf(-(ir + hr)));
    float z  = 1.f / (1.f + expf(-(iz + hz)));
    float nn = tanhf(in_ + r * hn);
    float hprev = g_mol[i];
    float hnew  = (1.f - z) * nn + z * hprev;
    hnew = fmaxf(hnew, 0.f);
    g_mol[i] = hnew;
    if (write_out) out_mol[i] = hnew;
}

// ---------------- launch ----------------
extern "C" void kernel_launch(void* const* d_in, const int* in_sizes, int n_in,
                              void* d_out, int out_size)
{
    const float* h_nodes  = (const float*)d_in[0];
    const float* mol_feat = (const float*)d_in[1];
    const float* W_src    = (const float*)d_in[2];
    const float* b_src    = (const float*)d_in[3];
    const float* W_dst    = (const float*)d_in[4];
    const float* b_dst    = (const float*)d_in[5];
    const float* attn_a   = (const float*)d_in[6];
    const float* W_ih     = (const float*)d_in[7];
    const float* W_hh     = (const float*)d_in[8];
    const float* b_ih     = (const float*)d_in[9];
    const float* b_hh     = (const float*)d_in[10];
    const int*   src      = (const int*)d_in[11];
    const int*   dst      = (const int*)d_in[12];
    const int*   vnid     = (const int*)d_in[13];
    const int*   eids     = (const int*)d_in[14];
    float* out = (float*)d_out;

    cudaFuncSetAttribute(gemm_mma, cudaFuncAttributeMaxDynamicSharedMemorySize, GEMM_SMEM);

    {
        long tot = (long)NN * NH + (long)BB * NH;
        init_k<<<(int)((tot + 255) / 256), 256>>>(h_nodes, mol_feat);
    }
    {
        dim3 gr(HO / 32, NH / 32, 6);
        transpose_conv_k<<<gr, dim3(32, 8)>>>(W_src, W_dst);
    }

    __half* pBf = nullptr;
    cudaGetSymbolAddress((void**)&pBf, g_Bf);

    for (int t = 0; t < TSTEP; t++) {
        dim3 gg(HO / 128, NN / 128, 2);   // (48, 49, 2)
        size_t msz = (size_t)HO * NH;
        gemm_mma<<<gg, 256, GEMM_SMEM>>>(pBf + (size_t)(t * 2) * msz,
                                         b_src + (size_t)t * HO,
                                         b_dst + (size_t)t * HO);
        edge_logits_k<<<EE, 256>>>(src, dst, attn_a + (size_t)t * HEADS * NH);
        node_aggregate_k<<<NN, 256>>>(src, dst);
        attn_gather_k<<<(BB * NATOM + 255) / 256, 256>>>(eids, out, t);
        gru_gemm_k<<<BB * H3 / 8, 256>>>(W_ih + (size_t)t * H3 * NH,
                                         W_hh + (size_t)t * H3 * NH,
                                         b_ih + (size_t)t * H3,
                                         b_hh + (size_t)t * H3, vnid);
        gru_combine_k<<<BB * NH / 256, 256>>>(out, t == TSTEP - 1);
    }
}